// round 1
// baseline (speedup 1.0000x reference)
#include <cuda_runtime.h>
#include <math.h>

#define B_   32
#define SEQ  512
#define PRED 96
#define CIN  32
#define D_   512
#define H_   8
#define E_   64
#define DFF  2048
#define NTOK (B_*SEQ)   // 16384

// ---------------- scratch (static device allocations are allowed) ----------------
__device__ float g_xn[B_*SEQ*CIN];
__device__ float g_mean[B_*CIN];
__device__ float g_std[B_*CIN];
__device__ float g_xcat[NTOK*96];
__device__ float g_wcat[D_*96];
__device__ float g_h[NTOK*D_];
__device__ float g_q[NTOK*D_];
__device__ float g_k[NTOK*D_];
__device__ float g_v[NTOK*D_];
__device__ float g_attn[NTOK*D_];
__device__ float g_tmp[NTOK*D_];
__device__ float g_x1[NTOK*D_];
__device__ float g_ff[NTOK*DFF];
__device__ float g_dec1[NTOK*CIN];

// ---------------- helpers ----------------
__device__ __forceinline__ float blockSum128(float v, float* sbuf) {
    #pragma unroll
    for (int o = 16; o; o >>= 1) v += __shfl_xor_sync(0xffffffffu, v, o);
    int w = threadIdx.x >> 5;
    if ((threadIdx.x & 31) == 0) sbuf[w] = v;
    __syncthreads();
    v = sbuf[0] + sbuf[1] + sbuf[2] + sbuf[3];
    __syncthreads();
    return v;
}

// ---------------- instance norm over time, per (b,c) ----------------
__global__ void instnorm_kernel(const float* __restrict__ x) {
    __shared__ float sbuf[4];
    int b = blockIdx.x >> 5, c = blockIdx.x & 31;
    int t = threadIdx.x;                       // 128 threads
    float v[4];
    #pragma unroll
    for (int u = 0; u < 4; ++u)
        v[u] = x[((size_t)b*SEQ + t + 128*u)*CIN + c];
    float s = v[0]+v[1]+v[2]+v[3];
    s = blockSum128(s, sbuf);
    float mean = s * (1.0f/SEQ);
    float qq = 0.f;
    #pragma unroll
    for (int u = 0; u < 4; ++u) { float d = v[u]-mean; qq += d*d; }
    qq = blockSum128(qq, sbuf);
    float sd = sqrtf(qq*(1.0f/SEQ) + 1e-5f);
    float inv = 1.0f/sd;
    #pragma unroll
    for (int u = 0; u < 4; ++u)
        g_xn[((size_t)b*SEQ + t + 128*u)*CIN + c] = (v[u]-mean)*inv;
    if (t == 0) { g_mean[b*CIN+c] = mean; g_std[b*CIN+c] = sd; }
}

// ---------------- build circular-conv input matrix [NTOK, 96] ----------------
__global__ void xcat_kernel() {
    int idx = blockIdx.x*256 + threadIdx.x;    // NTOK*CIN threads
    if (idx >= NTOK*CIN) return;
    int c = idx & 31, n = idx >> 5;
    int b = n >> 9, l = n & 511;
    #pragma unroll
    for (int kk = 0; kk < 3; ++kk) {
        int ls = (l + kk - 1 + SEQ) & (SEQ-1);
        g_xcat[(size_t)n*96 + kk*32 + c] = g_xn[((size_t)b*SEQ + ls)*CIN + c];
    }
}

// ---------------- rearrange conv weight into [D, 96] K-contiguous ----------------
__global__ void wcat_kernel(const float* __restrict__ cw) {
    int idx = blockIdx.x*256 + threadIdx.x;
    if (idx >= D_*96) return;
    int d = idx / 96, r = idx % 96;
    int kk = r >> 5, c = r & 31;
    g_wcat[idx] = cw[(d*CIN + c)*3 + kk];
}

// ---------------- generic tiled SGEMM: C[M,N] = A[M,K] * B[N,K]^T (+bias, epilogue) ----------------
enum { EPI_PLAIN = 0, EPI_GELU = 1, EPI_QKV = 2, EPI_EMB = 3 };

template<int EPI>
__global__ void __launch_bounds__(256, 2) gemm_kernel(
    const float* __restrict__ A, const float* __restrict__ Bm,
    const float* __restrict__ bias, float* __restrict__ C,
    int M, int N, int K)
{
    __shared__ float As[16][132];
    __shared__ float Bs[16][132];
    int tid = threadIdx.x;
    int m0 = blockIdx.y * 128, n0 = blockIdx.x * 128;
    int tx = tid & 15, ty = tid >> 4;
    int lr = tid >> 2;               // 0..63
    int lq = (tid & 3) * 4;          // 0,4,8,12

    float acc[8][8];
    #pragma unroll
    for (int i = 0; i < 8; ++i)
        #pragma unroll
        for (int j = 0; j < 8; ++j) acc[i][j] = 0.f;

    for (int k0 = 0; k0 < K; k0 += 16) {
        #pragma unroll
        for (int hh = 0; hh < 2; ++hh) {
            int r = lr + hh*64;
            int gm = m0 + r;
            float4 va = make_float4(0.f,0.f,0.f,0.f);
            if (gm < M) va = *(const float4*)(A + (size_t)gm*K + k0 + lq);
            As[lq+0][r] = va.x; As[lq+1][r] = va.y; As[lq+2][r] = va.z; As[lq+3][r] = va.w;
            int gn = n0 + r;
            float4 vb = make_float4(0.f,0.f,0.f,0.f);
            if (gn < N) vb = *(const float4*)(Bm + (size_t)gn*K + k0 + lq);
            Bs[lq+0][r] = vb.x; Bs[lq+1][r] = vb.y; Bs[lq+2][r] = vb.z; Bs[lq+3][r] = vb.w;
        }
        __syncthreads();
        #pragma unroll
        for (int kk = 0; kk < 16; ++kk) {
            float4 a0 = *(const float4*)(&As[kk][ty*4]);
            float4 a1 = *(const float4*)(&As[kk][64 + ty*4]);
            float4 b0 = *(const float4*)(&Bs[kk][tx*4]);
            float4 b1 = *(const float4*)(&Bs[kk][64 + tx*4]);
            float av[8] = {a0.x,a0.y,a0.z,a0.w,a1.x,a1.y,a1.z,a1.w};
            float bv[8] = {b0.x,b0.y,b0.z,b0.w,b1.x,b1.y,b1.z,b1.w};
            #pragma unroll
            for (int i = 0; i < 8; ++i)
                #pragma unroll
                for (int j = 0; j < 8; ++j)
                    acc[i][j] = fmaf(av[i], bv[j], acc[i][j]);
        }
        __syncthreads();
    }

    #pragma unroll
    for (int i = 0; i < 8; ++i) {
        int mi = (i < 4) ? (ty*4 + i) : (64 + ty*4 + i - 4);
        int m = m0 + mi;
        if (m >= M) continue;
        #pragma unroll
        for (int j = 0; j < 8; ++j) {
            int nj = (j < 4) ? (tx*4 + j) : (64 + tx*4 + j - 4);
            int n = n0 + nj;
            if (n >= N) continue;
            float val = acc[i][j];
            if (EPI == EPI_EMB) {
                // add sinusoidal positional embedding, no bias
                int l = m & (SEQ-1);
                float fr = expf(-(float)(n & ~1) * (9.210340371976184f / (float)D_));
                float ang = (float)l * fr;
                val += (n & 1) ? cosf(ang) : sinf(ang);
                C[(size_t)m*N + n] = val;
            } else {
                val += bias[n];
                if (EPI == EPI_GELU)
                    val = 0.5f * val * (1.0f + erff(val * 0.7071067811865475f));
                if (EPI == EPI_QKV) {
                    int bb = m >> 9, l = m & 511, hh2 = n >> 6, e = n & 63;
                    C[(((size_t)(bb*H_ + hh2))*SEQ + l)*E_ + e] = val;   // [B,H,S,E]
                } else {
                    C[(size_t)m*N + n] = val;
                }
            }
        }
    }
}

// ---------------- fused flash attention: [B,H,S,E] -> attn [B,S,D] ----------------
__global__ void __launch_bounds__(256) attn_kernel() {
    extern __shared__ float sm[];
    const int LD = 68;
    float* Qs = sm;
    float* KP = sm + 64*LD;          // K tile, reused for P tile
    float* Vt = sm + 2*64*LD;        // V tile transposed [e][s]
    int tid = threadIdx.x;
    int tx = tid & 15, ty = tid >> 4;
    int bh = blockIdx.y, qt = blockIdx.x;
    const float* qb  = g_q + ((size_t)bh*SEQ + qt*64) * E_;
    const float* kb0 = g_k + (size_t)bh*SEQ*E_;
    const float* vb0 = g_v + (size_t)bh*SEQ*E_;

    #pragma unroll
    for (int u = 0; u < 4; ++u) {
        int idx = tid + 256*u;
        int row = idx >> 4, e4 = idx & 15;
        *(float4*)&Qs[row*LD + e4*4] = *(const float4*)(qb + row*64 + e4*4);
    }

    float mrun[4], lrun[4], acc[4][4];
    #pragma unroll
    for (int i = 0; i < 4; ++i) {
        mrun[i] = -1e30f; lrun[i] = 0.f;
        #pragma unroll
        for (int j = 0; j < 4; ++j) acc[i][j] = 0.f;
    }

    for (int t = 0; t < 8; ++t) {
        const float* kb = kb0 + (size_t)t*64*E_;
        const float* vb = vb0 + (size_t)t*64*E_;
        #pragma unroll
        for (int u = 0; u < 4; ++u) {
            int idx = tid + 256*u;
            int row = idx >> 4, e4 = idx & 15;
            *(float4*)&KP[row*LD + e4*4] = *(const float4*)(kb + row*64 + e4*4);
            float4 vv = *(const float4*)(vb + row*64 + e4*4);
            Vt[(e4*4+0)*LD + row] = vv.x;
            Vt[(e4*4+1)*LD + row] = vv.y;
            Vt[(e4*4+2)*LD + row] = vv.z;
            Vt[(e4*4+3)*LD + row] = vv.w;
        }
        __syncthreads();

        float s[4][4] = {};
        #pragma unroll
        for (int e4 = 0; e4 < 16; ++e4) {
            float4 qa[4], ka[4];
            #pragma unroll
            for (int i = 0; i < 4; ++i) qa[i] = *(const float4*)&Qs[(ty+16*i)*LD + e4*4];
            #pragma unroll
            for (int j = 0; j < 4; ++j) ka[j] = *(const float4*)&KP[(tx+16*j)*LD + e4*4];
            #pragma unroll
            for (int i = 0; i < 4; ++i)
                #pragma unroll
                for (int j = 0; j < 4; ++j)
                    s[i][j] += qa[i].x*ka[j].x + qa[i].y*ka[j].y + qa[i].z*ka[j].z + qa[i].w*ka[j].w;
        }
        __syncthreads();                 // done reading K tile

        #pragma unroll
        for (int i = 0; i < 4; ++i) {
            float mt = -1e30f;
            #pragma unroll
            for (int j = 0; j < 4; ++j) { s[i][j] *= 0.125f; mt = fmaxf(mt, s[i][j]); }
            #pragma unroll
            for (int o = 8; o; o >>= 1) mt = fmaxf(mt, __shfl_xor_sync(0xffffffffu, mt, o, 16));
            float mnew  = fmaxf(mrun[i], mt);
            float alpha = expf(mrun[i] - mnew);
            lrun[i] *= alpha;
            #pragma unroll
            for (int j = 0; j < 4; ++j) acc[i][j] *= alpha;
            float rs = 0.f;
            #pragma unroll
            for (int j = 0; j < 4; ++j) { float p = expf(s[i][j] - mnew); s[i][j] = p; rs += p; }
            #pragma unroll
            for (int o = 8; o; o >>= 1) rs += __shfl_xor_sync(0xffffffffu, rs, o, 16);
            lrun[i] += rs;
            mrun[i] = mnew;
            #pragma unroll
            for (int j = 0; j < 4; ++j) KP[(ty+16*i)*LD + (tx+16*j)] = s[i][j];
        }
        __syncthreads();                 // P visible

        #pragma unroll
        for (int k4 = 0; k4 < 16; ++k4) {
            float4 pa[4], va[4];
            #pragma unroll
            for (int i = 0; i < 4; ++i) pa[i] = *(const float4*)&KP[(ty+16*i)*LD + k4*4];
            #pragma unroll
            for (int j = 0; j < 4; ++j) va[j] = *(const float4*)&Vt[(tx+16*j)*LD + k4*4];
            #pragma unroll
            for (int i = 0; i < 4; ++i)
                #pragma unroll
                for (int j = 0; j < 4; ++j)
                    acc[i][j] += pa[i].x*va[j].x + pa[i].y*va[j].y + pa[i].z*va[j].z + pa[i].w*va[j].w;
        }
        __syncthreads();                 // done with KP/Vt before next load
    }

    int b = bh >> 3, hh = bh & 7;
    #pragma unroll
    for (int i = 0; i < 4; ++i) {
        int l = qt*64 + ty + 16*i;
        float inv = 1.0f / lrun[i];
        #pragma unroll
        for (int j = 0; j < 4; ++j) {
            int d = hh*64 + tx + 16*j;
            g_attn[((size_t)(b*SEQ + l))*D_ + d] = acc[i][j] * inv;
        }
    }
}

// ---------------- fused (optional residual add) + LayerNorm over D=512 ----------------
__global__ void add_ln_kernel(const float* __restrict__ A, const float* __restrict__ R,
                              const float* __restrict__ g, const float* __restrict__ be,
                              float* __restrict__ out)
{
    __shared__ float sbuf[4];
    size_t n = blockIdx.x;
    int t = threadIdx.x;                 // 128 threads, one float4 each
    float4 v = ((const float4*)(A + n*D_))[t];
    if (R) {
        float4 r = ((const float4*)(R + n*D_))[t];
        v.x += r.x; v.y += r.y; v.z += r.z; v.w += r.w;
    }
    float s = v.x + v.y + v.z + v.w;
    s = blockSum128(s, sbuf);
    float mean = s * (1.0f/D_);
    float dx = v.x-mean, dy = v.y-mean, dz = v.z-mean, dw = v.w-mean;
    float qq = dx*dx + dy*dy + dz*dz + dw*dw;
    qq = blockSum128(qq, sbuf);
    float rstd = rsqrtf(qq*(1.0f/D_) + 1e-5f);
    float4 gv = ((const float4*)g)[t];
    float4 bv = ((const float4*)be)[t];
    float4 o;
    o.x = dx*rstd*gv.x + bv.x;
    o.y = dy*rstd*gv.y + bv.y;
    o.z = dz*rstd*gv.z + bv.z;
    o.w = dw*rstd*gv.w + bv.w;
    ((float4*)(out + n*D_))[t] = o;
}

// ---------------- time projection + de-normalization ----------------
__global__ void timeproj_kernel(const float* __restrict__ Wt, const float* __restrict__ bt,
                                float* __restrict__ out)
{
    __shared__ float sw[512];
    __shared__ float sred[4][32];
    int bp = blockIdx.x;
    int b = bp / PRED, p = bp % PRED;
    int t = threadIdx.x;                 // 128
    for (int j = t; j < 512; j += 128) sw[j] = Wt[p*512 + j];
    __syncthreads();
    int c = t & 31, part = t >> 5;
    const float* dp = g_dec1 + (size_t)b*SEQ*CIN;
    float s = 0.f;
    for (int l = part*128; l < part*128 + 128; ++l)
        s += dp[l*CIN + c] * sw[l];
    sred[part][c] = s;
    __syncthreads();
    if (t < 32) {
        float tot = sred[0][c] + sred[1][c] + sred[2][c] + sred[3][c] + bt[p];
        out[((size_t)b*PRED + p)*CIN + c] = tot * g_std[b*CIN+c] + g_mean[b*CIN+c];
    }
}

// ---------------- launch ----------------
extern "C" void kernel_launch(void* const* d_in, const int* in_sizes, int n_in,
                              void* d_out, int out_size)
{
    const float* x_enc  = (const float*)d_in[0];
    const float* conv_w = (const float*)d_in[1];
    const float* Wq = (const float*)d_in[2];
    const float* Wk = (const float*)d_in[3];
    const float* Wv = (const float*)d_in[4];
    const float* Wo = (const float*)d_in[5];
    const float* bq = (const float*)d_in[6];
    const float* bk = (const float*)d_in[7];
    const float* bv = (const float*)d_in[8];
    const float* bo = (const float*)d_in[9];
    const float* ff1_w = (const float*)d_in[10];
    const float* ff1_b = (const float*)d_in[11];
    const float* ff2_w = (const float*)d_in[12];
    const float* ff2_b = (const float*)d_in[13];
    const float* n1_g = (const float*)d_in[14];
    const float* n1_b = (const float*)d_in[15];
    const float* n2_g = (const float*)d_in[16];
    const float* n2_b = (const float*)d_in[17];
    const float* fn_g = (const float*)d_in[18];
    const float* fn_b = (const float*)d_in[19];
    const float* Wch  = (const float*)d_in[20];
    const float* bch  = (const float*)d_in[21];
    const float* Wt   = (const float*)d_in[22];
    const float* bt   = (const float*)d_in[23];
    float* out = (float*)d_out;

    float *xcat,*wcat,*h,*q,*k,*v,*attn,*tmp,*x1,*ff,*dec1;
    cudaGetSymbolAddress((void**)&xcat, g_xcat);
    cudaGetSymbolAddress((void**)&wcat, g_wcat);
    cudaGetSymbolAddress((void**)&h,    g_h);
    cudaGetSymbolAddress((void**)&q,    g_q);
    cudaGetSymbolAddress((void**)&k,    g_k);
    cudaGetSymbolAddress((void**)&v,    g_v);
    cudaGetSymbolAddress((void**)&attn, g_attn);
    cudaGetSymbolAddress((void**)&tmp,  g_tmp);
    cudaGetSymbolAddress((void**)&x1,   g_x1);
    cudaGetSymbolAddress((void**)&ff,   g_ff);
    cudaGetSymbolAddress((void**)&dec1, g_dec1);

    const int ATTN_SMEM = 3*64*68*4;     // 52224 bytes
    cudaFuncSetAttribute(attn_kernel, cudaFuncAttributeMaxDynamicSharedMemorySize, ATTN_SMEM);

    instnorm_kernel<<<B_*CIN, 128>>>(x_enc);
    xcat_kernel<<<(NTOK*CIN)/256, 256>>>();
    wcat_kernel<<<(D_*96 + 255)/256, 256>>>(conv_w);
    gemm_kernel<EPI_EMB><<<dim3(4,128), 256>>>(xcat, wcat, nullptr, h, NTOK, D_, 96);

    for (int i = 0; i < 3; ++i) {
        size_t WO = (size_t)i*D_*D_;
        gemm_kernel<EPI_QKV><<<dim3(4,128), 256>>>(h, Wq+WO, bq+i*D_, q, NTOK, D_, D_);
        gemm_kernel<EPI_QKV><<<dim3(4,128), 256>>>(h, Wk+WO, bk+i*D_, k, NTOK, D_, D_);
        gemm_kernel<EPI_QKV><<<dim3(4,128), 256>>>(h, Wv+WO, bv+i*D_, v, NTOK, D_, D_);
        attn_kernel<<<dim3(8, B_*H_), 256, ATTN_SMEM>>>();
        gemm_kernel<EPI_PLAIN><<<dim3(4,128), 256>>>(attn, Wo+WO, bo+i*D_, tmp, NTOK, D_, D_);
        add_ln_kernel<<<NTOK, 128>>>(h, tmp, n1_g+i*D_, n1_b+i*D_, x1);
        gemm_kernel<EPI_GELU><<<dim3(16,128), 256>>>(x1, ff1_w+(size_t)i*DFF*D_, ff1_b+i*DFF, ff, NTOK, DFF, D_);
        gemm_kernel<EPI_PLAIN><<<dim3(4,128), 256>>>(ff, ff2_w+(size_t)i*D_*DFF, ff2_b+i*D_, tmp, NTOK, D_, DFF);
        add_ln_kernel<<<NTOK, 128>>>(x1, tmp, n2_g+i*D_, n2_b+i*D_, h);
    }

    add_ln_kernel<<<NTOK, 128>>>(h, nullptr, fn_g, fn_b, h);
    gemm_kernel<EPI_PLAIN><<<dim3(1,128), 256>>>(h, Wch, bch, dec1, NTOK, CIN, D_);
    timeproj_kernel<<<B_*PRED, 128>>>(Wt, bt, out);
}

// round 3
// speedup vs baseline: 2.1491x; 2.1491x over previous
#include <cuda_runtime.h>
#include <cstdint>
#include <math.h>

#define B_   32
#define SEQ  512
#define PRED 96
#define CIN  32
#define D_   512
#define H_   8
#define E_   64
#define DFF  2048
#define NTOK (B_*SEQ)   // 16384

// ---------------- scratch ----------------
__device__ float g_xn[B_*SEQ*CIN];
__device__ float g_mean[B_*CIN];
__device__ float g_std[B_*CIN];
__device__ float g_xcat[NTOK*96];
__device__ float g_wcat[D_*96];
__device__ float g_h[NTOK*D_];
__device__ float g_q[NTOK*D_];
__device__ float g_k[NTOK*D_];
__device__ float g_v[NTOK*D_];
__device__ float g_attn[NTOK*D_];
__device__ float g_tmp[NTOK*D_];
__device__ float g_x1[NTOK*D_];
__device__ float g_ff[NTOK*DFF];
__device__ float g_dec1[NTOK*CIN];

__device__ __forceinline__ uint32_t smem_u32(const void* p) {
    uint32_t a;
    asm("{ .reg .u64 t; cvta.to.shared.u64 t, %1; cvt.u32.u64 %0, t; }" : "=r"(a) : "l"(p));
    return a;
}
__device__ __forceinline__ uint32_t f2tf(float x) {
    uint32_t t;
    asm("cvt.rna.tf32.f32 %0, %1;" : "=r"(t) : "f"(x));
    return t;
}
__device__ __forceinline__ float lds_f32(uint32_t addr) {
    float v;
    asm volatile("ld.shared.f32 %0, [%1];" : "=f"(v) : "r"(addr));
    return v;
}
__device__ __forceinline__ void mma_tf32(float* c, const uint32_t* a, const uint32_t* b) {
    asm volatile(
        "mma.sync.aligned.m16n8k8.row.col.f32.tf32.tf32.f32 "
        "{%0,%1,%2,%3}, {%4,%5,%6,%7}, {%8,%9}, {%0,%1,%2,%3};"
        : "+f"(c[0]), "+f"(c[1]), "+f"(c[2]), "+f"(c[3])
        : "r"(a[0]), "r"(a[1]), "r"(a[2]), "r"(a[3]), "r"(b[0]), "r"(b[1]));
}

enum { EPI_PLAIN = 0, EPI_GELU = 1, EPI_QKV = 2, EPI_EMB = 3 };

// smem tile: 128 rows x 32 k-floats, row stride padded to 36 floats (144 B)
#define TILE_B 18432u
#define MM_SMEM (4*18432)

// ============ mma.sync tf32 GEMM: C[M,N] = A[M,K]*B[N,K]^T (+epilogue) ============
// M,N multiples of 128; K multiple of 32.
template<int EPI>
__global__ void __launch_bounds__(256, 2) mm_gemm(
    const float* __restrict__ A, const float* __restrict__ Bm,
    const float* __restrict__ bias, float* __restrict__ C,
    int M, int N, int K)
{
    extern __shared__ __align__(16) char smem[];
    uint32_t sb = smem_u32(smem);
    int tid = threadIdx.x, lane = tid & 31, wid = tid >> 5;
    int g = lane >> 2, tg = lane & 3;
    int wm = wid & 1, wn = wid >> 1;          // warp tile: rows wm*64, cols wn*32
    int m0 = blockIdx.y * 128, n0 = blockIdx.x * 128;
    int nch = K >> 5;

    float acc[4][4][4];
    #pragma unroll
    for (int i = 0; i < 4; ++i)
        #pragma unroll
        for (int j = 0; j < 4; ++j)
            #pragma unroll
            for (int e = 0; e < 4; ++e) acc[i][j][e] = 0.f;

    auto issue = [&](int c) {
        int p = c & 1;
        uint32_t abuf = sb + (uint32_t)p * 2u * TILE_B;
        uint32_t bbuf = abuf + TILE_B;
        const float* Ag = A + (size_t)m0 * K + c * 32;
        const float* Bg = Bm + (size_t)n0 * K + c * 32;
        #pragma unroll
        for (int u = 0; u < 4; ++u) {
            int slot = tid + 256 * u;         // 0..1023
            int r = slot >> 3, q = slot & 7;
            uint32_t so = (uint32_t)(r * 144 + q * 16);
            asm volatile("cp.async.cg.shared.global [%0], [%1], 16;"
                         :: "r"(abuf + so), "l"(Ag + (size_t)r * K + q * 4));
            asm volatile("cp.async.cg.shared.global [%0], [%1], 16;"
                         :: "r"(bbuf + so), "l"(Bg + (size_t)r * K + q * 4));
        }
        asm volatile("cp.async.commit_group;" ::: "memory");
    };

    issue(0);
    for (int c = 0; c < nch; ++c) {
        if (c + 1 < nch) {
            issue(c + 1);
            asm volatile("cp.async.wait_group 1;" ::: "memory");
        } else {
            asm volatile("cp.async.wait_group 0;" ::: "memory");
        }
        __syncthreads();

        int p = c & 1;
        uint32_t abuf = sb + (uint32_t)p * 2u * TILE_B;
        uint32_t bbuf = abuf + TILE_B;
        uint32_t arow = abuf + (uint32_t)((wm * 64 + g) * 144);
        uint32_t brow = bbuf + (uint32_t)((wn * 32 + g) * 144);

        #pragma unroll
        for (int s = 0; s < 4; ++s) {
            uint32_t ka = (uint32_t)((s * 8 + tg) * 4);
            uint32_t af[4][4];
            #pragma unroll
            for (int mi = 0; mi < 4; ++mi) {
                uint32_t ba = arow + (uint32_t)(mi * 16 * 144) + ka;
                af[mi][0] = f2tf(lds_f32(ba));
                af[mi][1] = f2tf(lds_f32(ba + 8 * 144));
                af[mi][2] = f2tf(lds_f32(ba + 16));
                af[mi][3] = f2tf(lds_f32(ba + 8 * 144 + 16));
            }
            uint32_t bf[4][2];
            #pragma unroll
            for (int ni = 0; ni < 4; ++ni) {
                uint32_t bbx = brow + (uint32_t)(ni * 8 * 144) + ka;
                bf[ni][0] = f2tf(lds_f32(bbx));
                bf[ni][1] = f2tf(lds_f32(bbx + 16));
            }
            #pragma unroll
            for (int mi = 0; mi < 4; ++mi)
                #pragma unroll
                for (int ni = 0; ni < 4; ++ni)
                    mma_tf32(acc[mi][ni], af[mi], bf[ni]);
        }
        __syncthreads();
    }

    // -------- epilogue --------
    #pragma unroll
    for (int mi = 0; mi < 4; ++mi) {
        #pragma unroll
        for (int rr = 0; rr < 2; ++rr) {
            int m = m0 + wm * 64 + mi * 16 + g + rr * 8;
            #pragma unroll
            for (int ni = 0; ni < 4; ++ni) {
                int n = n0 + wn * 32 + ni * 8 + tg * 2;
                float x0 = acc[mi][ni][rr * 2 + 0];
                float x1 = acc[mi][ni][rr * 2 + 1];
                if (EPI != EPI_EMB) {
                    float2 bv = *(const float2*)(bias + n);
                    x0 += bv.x; x1 += bv.y;
                }
                if (EPI == EPI_GELU) {
                    x0 = 0.5f * x0 * (1.0f + erff(x0 * 0.7071067811865475f));
                    x1 = 0.5f * x1 * (1.0f + erff(x1 * 0.7071067811865475f));
                }
                if (EPI == EPI_EMB) {
                    int l = m & (SEQ - 1);
                    float fr = expf(-(float)n * (9.210340371976184f / (float)D_)); // n even
                    float ang = (float)l * fr;
                    x0 += sinf(ang);
                    x1 += cosf(ang);
                }
                if (EPI == EPI_QKV) {
                    int bb2 = m >> 9, l = m & 511, hh = n >> 6, e = n & 63;
                    float* op = C + (((size_t)(bb2 * H_ + hh)) * SEQ + l) * E_ + e;
                    *(float2*)op = make_float2(x0, x1);
                } else {
                    *(float2*)(C + (size_t)m * N + n) = make_float2(x0, x1);
                }
            }
        }
    }
}

// ---------------- helpers ----------------
__device__ __forceinline__ float blockSum128(float v, float* sbuf) {
    #pragma unroll
    for (int o = 16; o; o >>= 1) v += __shfl_xor_sync(0xffffffffu, v, o);
    int w = threadIdx.x >> 5;
    if ((threadIdx.x & 31) == 0) sbuf[w] = v;
    __syncthreads();
    v = sbuf[0] + sbuf[1] + sbuf[2] + sbuf[3];
    __syncthreads();
    return v;
}

// ---------------- instance norm over time, per (b,c) ----------------
__global__ void instnorm_kernel(const float* __restrict__ x) {
    __shared__ float sbuf[4];
    int b = blockIdx.x >> 5, c = blockIdx.x & 31;
    int t = threadIdx.x;
    float v[4];
    #pragma unroll
    for (int u = 0; u < 4; ++u)
        v[u] = x[((size_t)b*SEQ + t + 128*u)*CIN + c];
    float s = v[0]+v[1]+v[2]+v[3];
    s = blockSum128(s, sbuf);
    float mean = s * (1.0f/SEQ);
    float qq = 0.f;
    #pragma unroll
    for (int u = 0; u < 4; ++u) { float d = v[u]-mean; qq += d*d; }
    qq = blockSum128(qq, sbuf);
    float sd = sqrtf(qq*(1.0f/SEQ) + 1e-5f);
    float inv = 1.0f/sd;
    #pragma unroll
    for (int u = 0; u < 4; ++u)
        g_xn[((size_t)b*SEQ + t + 128*u)*CIN + c] = (v[u]-mean)*inv;
    if (t == 0) { g_mean[b*CIN+c] = mean; g_std[b*CIN+c] = sd; }
}

// ---------------- build circular-conv input matrix [NTOK, 96] ----------------
__global__ void xcat_kernel() {
    int idx = blockIdx.x*256 + threadIdx.x;
    if (idx >= NTOK*CIN) return;
    int c = idx & 31, n = idx >> 5;
    int b = n >> 9, l = n & 511;
    #pragma unroll
    for (int kk = 0; kk < 3; ++kk) {
        int ls = (l + kk - 1 + SEQ) & (SEQ-1);
        g_xcat[(size_t)n*96 + kk*32 + c] = g_xn[((size_t)b*SEQ + ls)*CIN + c];
    }
}

// ---------------- rearrange conv weight into [D, 96] K-contiguous ----------------
__global__ void wcat_kernel(const float* __restrict__ cw) {
    int idx = blockIdx.x*256 + threadIdx.x;
    if (idx >= D_*96) return;
    int d = idx / 96, r = idx % 96;
    int kk = r >> 5, c = r & 31;
    g_wcat[idx] = cw[(d*CIN + c)*3 + kk];
}

// ---------------- fp32 SGEMM (tiny final channel projection) ----------------
__global__ void __launch_bounds__(256, 2) gemm_f32(
    const float* __restrict__ A, const float* __restrict__ Bm,
    const float* __restrict__ bias, float* __restrict__ C,
    int M, int N, int K)
{
    __shared__ float As[16][132];
    __shared__ float Bs[16][132];
    int tid = threadIdx.x;
    int m0 = blockIdx.y * 128, n0 = blockIdx.x * 128;
    int tx = tid & 15, ty = tid >> 4;
    int lr = tid >> 2;
    int lq = (tid & 3) * 4;

    float acc[8][8];
    #pragma unroll
    for (int i = 0; i < 8; ++i)
        #pragma unroll
        for (int j = 0; j < 8; ++j) acc[i][j] = 0.f;

    for (int k0 = 0; k0 < K; k0 += 16) {
        #pragma unroll
        for (int hh = 0; hh < 2; ++hh) {
            int r = lr + hh*64;
            int gm = m0 + r;
            float4 va = make_float4(0.f,0.f,0.f,0.f);
            if (gm < M) va = *(const float4*)(A + (size_t)gm*K + k0 + lq);
            As[lq+0][r] = va.x; As[lq+1][r] = va.y; As[lq+2][r] = va.z; As[lq+3][r] = va.w;
            int gn = n0 + r;
            float4 vb = make_float4(0.f,0.f,0.f,0.f);
            if (gn < N) vb = *(const float4*)(Bm + (size_t)gn*K + k0 + lq);
            Bs[lq+0][r] = vb.x; Bs[lq+1][r] = vb.y; Bs[lq+2][r] = vb.z; Bs[lq+3][r] = vb.w;
        }
        __syncthreads();
        #pragma unroll
        for (int kk = 0; kk < 16; ++kk) {
            float4 a0 = *(const float4*)(&As[kk][ty*4]);
            float4 a1 = *(const float4*)(&As[kk][64 + ty*4]);
            float4 b0 = *(const float4*)(&Bs[kk][tx*4]);
            float4 b1 = *(const float4*)(&Bs[kk][64 + tx*4]);
            float av[8] = {a0.x,a0.y,a0.z,a0.w,a1.x,a1.y,a1.z,a1.w};
            float bv[8] = {b0.x,b0.y,b0.z,b0.w,b1.x,b1.y,b1.z,b1.w};
            #pragma unroll
            for (int i = 0; i < 8; ++i)
                #pragma unroll
                for (int j = 0; j < 8; ++j)
                    acc[i][j] = fmaf(av[i], bv[j], acc[i][j]);
        }
        __syncthreads();
    }

    #pragma unroll
    for (int i = 0; i < 8; ++i) {
        int mi = (i < 4) ? (ty*4 + i) : (64 + ty*4 + i - 4);
        int m = m0 + mi;
        if (m >= M) continue;
        #pragma unroll
        for (int j = 0; j < 8; ++j) {
            int nj = (j < 4) ? (tx*4 + j) : (64 + tx*4 + j - 4);
            int n = n0 + nj;
            if (n >= N) continue;
            C[(size_t)m*N + n] = acc[i][j] + bias[n];
        }
    }
}

// ---------------- fused flash attention: [B,H,S,E] -> attn [B,S,D] ----------------
__global__ void __launch_bounds__(256) attn_kernel() {
    extern __shared__ float sm[];
    const int LD = 68;
    float* Qs = sm;
    float* KP = sm + 64*LD;
    float* Vt = sm + 2*64*LD;
    int tid = threadIdx.x;
    int tx = tid & 15, ty = tid >> 4;
    int bh = blockIdx.y, qt = blockIdx.x;
    const float* qb  = g_q + ((size_t)bh*SEQ + qt*64) * E_;
    const float* kb0 = g_k + (size_t)bh*SEQ*E_;
    const float* vb0 = g_v + (size_t)bh*SEQ*E_;

    #pragma unroll
    for (int u = 0; u < 4; ++u) {
        int idx = tid + 256*u;
        int row = idx >> 4, e4 = idx & 15;
        *(float4*)&Qs[row*LD + e4*4] = *(const float4*)(qb + row*64 + e4*4);
    }

    float mrun[4], lrun[4], acc[4][4];
    #pragma unroll
    for (int i = 0; i < 4; ++i) {
        mrun[i] = -1e30f; lrun[i] = 0.f;
        #pragma unroll
        for (int j = 0; j < 4; ++j) acc[i][j] = 0.f;
    }

    for (int t = 0; t < 8; ++t) {
        const float* kb = kb0 + (size_t)t*64*E_;
        const float* vb = vb0 + (size_t)t*64*E_;
        #pragma unroll
        for (int u = 0; u < 4; ++u) {
            int idx = tid + 256*u;
            int row = idx >> 4, e4 = idx & 15;
            *(float4*)&KP[row*LD + e4*4] = *(const float4*)(kb + row*64 + e4*4);
            float4 vv = *(const float4*)(vb + row*64 + e4*4);
            Vt[(e4*4+0)*LD + row] = vv.x;
            Vt[(e4*4+1)*LD + row] = vv.y;
            Vt[(e4*4+2)*LD + row] = vv.z;
            Vt[(e4*4+3)*LD + row] = vv.w;
        }
        __syncthreads();

        float s[4][4] = {};
        #pragma unroll
        for (int e4 = 0; e4 < 16; ++e4) {
            float4 qa[4], ka[4];
            #pragma unroll
            for (int i = 0; i < 4; ++i) qa[i] = *(const float4*)&Qs[(ty+16*i)*LD + e4*4];
            #pragma unroll
            for (int j = 0; j < 4; ++j) ka[j] = *(const float4*)&KP[(tx+16*j)*LD + e4*4];
            #pragma unroll
            for (int i = 0; i < 4; ++i)
                #pragma unroll
                for (int j = 0; j < 4; ++j)
                    s[i][j] += qa[i].x*ka[j].x + qa[i].y*ka[j].y + qa[i].z*ka[j].z + qa[i].w*ka[j].w;
        }
        __syncthreads();

        #pragma unroll
        for (int i = 0; i < 4; ++i) {
            float mt = -1e30f;
            #pragma unroll
            for (int j = 0; j < 4; ++j) { s[i][j] *= 0.125f; mt = fmaxf(mt, s[i][j]); }
            #pragma unroll
            for (int o = 8; o; o >>= 1) mt = fmaxf(mt, __shfl_xor_sync(0xffffffffu, mt, o, 16));
            float mnew  = fmaxf(mrun[i], mt);
            float alpha = expf(mrun[i] - mnew);
            lrun[i] *= alpha;
            #pragma unroll
            for (int j = 0; j < 4; ++j) acc[i][j] *= alpha;
            float rs = 0.f;
            #pragma unroll
            for (int j = 0; j < 4; ++j) { float p = expf(s[i][j] - mnew); s[i][j] = p; rs += p; }
            #pragma unroll
            for (int o = 8; o; o >>= 1) rs += __shfl_xor_sync(0xffffffffu, rs, o, 16);
            lrun[i] += rs;
            mrun[i] = mnew;
            #pragma unroll
            for (int j = 0; j < 4; ++j) KP[(ty+16*i)*LD + (tx+16*j)] = s[i][j];
        }
        __syncthreads();

        #pragma unroll
        for (int k4 = 0; k4 < 16; ++k4) {
            float4 pa[4], va[4];
            #pragma unroll
            for (int i = 0; i < 4; ++i) pa[i] = *(const float4*)&KP[(ty+16*i)*LD + k4*4];
            #pragma unroll
            for (int j = 0; j < 4; ++j) va[j] = *(const float4*)&Vt[(tx+16*j)*LD + k4*4];
            #pragma unroll
            for (int i = 0; i < 4; ++i)
                #pragma unroll
                for (int j = 0; j < 4; ++j)
                    acc[i][j] += pa[i].x*va[j].x + pa[i].y*va[j].y + pa[i].z*va[j].z + pa[i].w*va[j].w;
        }
        __syncthreads();
    }

    int b = bh >> 3, hh = bh & 7;
    #pragma unroll
    for (int i = 0; i < 4; ++i) {
        int l = qt*64 + ty + 16*i;
        float inv = 1.0f / lrun[i];
        #pragma unroll
        for (int j = 0; j < 4; ++j) {
            int d = hh*64 + tx + 16*j;
            g_attn[((size_t)(b*SEQ + l))*D_ + d] = acc[i][j] * inv;
        }
    }
}

// ---------------- fused (optional residual add) + LayerNorm over D=512 ----------------
__global__ void add_ln_kernel(const float* __restrict__ A, const float* __restrict__ R,
                              const float* __restrict__ g, const float* __restrict__ be,
                              float* __restrict__ out)
{
    __shared__ float sbuf[4];
    size_t n = blockIdx.x;
    int t = threadIdx.x;
    float4 v = ((const float4*)(A + n*D_))[t];
    if (R) {
        float4 r = ((const float4*)(R + n*D_))[t];
        v.x += r.x; v.y += r.y; v.z += r.z; v.w += r.w;
    }
    float s = v.x + v.y + v.z + v.w;
    s = blockSum128(s, sbuf);
    float mean = s * (1.0f/D_);
    float dx = v.x-mean, dy = v.y-mean, dz = v.z-mean, dw = v.w-mean;
    float qq = dx*dx + dy*dy + dz*dz + dw*dw;
    qq = blockSum128(qq, sbuf);
    float rstd = rsqrtf(qq*(1.0f/D_) + 1e-5f);
    float4 gv = ((const float4*)g)[t];
    float4 bv = ((const float4*)be)[t];
    float4 o;
    o.x = dx*rstd*gv.x + bv.x;
    o.y = dy*rstd*gv.y + bv.y;
    o.z = dz*rstd*gv.z + bv.z;
    o.w = dw*rstd*gv.w + bv.w;
    ((float4*)(out + n*D_))[t] = o;
}

// ---------------- time projection + de-normalization ----------------
__global__ void timeproj_kernel(const float* __restrict__ Wt, const float* __restrict__ bt,
                                float* __restrict__ out)
{
    __shared__ float sw[512];
    __shared__ float sred[4][32];
    int bp = blockIdx.x;
    int b = bp / PRED, p = bp % PRED;
    int t = threadIdx.x;
    for (int j = t; j < 512; j += 128) sw[j] = Wt[p*512 + j];
    __syncthreads();
    int c = t & 31, part = t >> 5;
    const float* dp = g_dec1 + (size_t)b*SEQ*CIN;
    float s = 0.f;
    for (int l = part*128; l < part*128 + 128; ++l)
        s += dp[l*CIN + c] * sw[l];
    sred[part][c] = s;
    __syncthreads();
    if (t < 32) {
        float tot = sred[0][c] + sred[1][c] + sred[2][c] + sred[3][c] + bt[p];
        out[((size_t)b*PRED + p)*CIN + c] = tot * g_std[b*CIN+c] + g_mean[b*CIN+c];
    }
}

// ---------------- launch ----------------
extern "C" void kernel_launch(void* const* d_in, const int* in_sizes, int n_in,
                              void* d_out, int out_size)
{
    const float* x_enc  = (const float*)d_in[0];
    const float* conv_w = (const float*)d_in[1];
    const float* Wq = (const float*)d_in[2];
    const float* Wk = (const float*)d_in[3];
    const float* Wv = (const float*)d_in[4];
    const float* Wo = (const float*)d_in[5];
    const float* bq = (const float*)d_in[6];
    const float* bk = (const float*)d_in[7];
    const float* bv = (const float*)d_in[8];
    const float* bo = (const float*)d_in[9];
    const float* ff1_w = (const float*)d_in[10];
    const float* ff1_b = (const float*)d_in[11];
    const float* ff2_w = (const float*)d_in[12];
    const float* ff2_b = (const float*)d_in[13];
    const float* n1_g = (const float*)d_in[14];
    const float* n1_b = (const float*)d_in[15];
    const float* n2_g = (const float*)d_in[16];
    const float* n2_b = (const float*)d_in[17];
    const float* fn_g = (const float*)d_in[18];
    const float* fn_b = (const float*)d_in[19];
    const float* Wch  = (const float*)d_in[20];
    const float* bch  = (const float*)d_in[21];
    const float* Wt   = (const float*)d_in[22];
    const float* bt   = (const float*)d_in[23];
    float* out = (float*)d_out;

    float *xcat,*wcat,*h,*q,*k,*v,*attn,*tmp,*x1,*ff,*dec1;
    cudaGetSymbolAddress((void**)&xcat, g_xcat);
    cudaGetSymbolAddress((void**)&wcat, g_wcat);
    cudaGetSymbolAddress((void**)&h,    g_h);
    cudaGetSymbolAddress((void**)&q,    g_q);
    cudaGetSymbolAddress((void**)&k,    g_k);
    cudaGetSymbolAddress((void**)&v,    g_v);
    cudaGetSymbolAddress((void**)&attn, g_attn);
    cudaGetSymbolAddress((void**)&tmp,  g_tmp);
    cudaGetSymbolAddress((void**)&x1,   g_x1);
    cudaGetSymbolAddress((void**)&ff,   g_ff);
    cudaGetSymbolAddress((void**)&dec1, g_dec1);

    const int ATTN_SMEM = 3*64*68*4;
    cudaFuncSetAttribute(attn_kernel, cudaFuncAttributeMaxDynamicSharedMemorySize, ATTN_SMEM);
    cudaFuncSetAttribute(mm_gemm<EPI_PLAIN>, cudaFuncAttributeMaxDynamicSharedMemorySize, MM_SMEM);
    cudaFuncSetAttribute(mm_gemm<EPI_GELU>,  cudaFuncAttributeMaxDynamicSharedMemorySize, MM_SMEM);
    cudaFuncSetAttribute(mm_gemm<EPI_QKV>,   cudaFuncAttributeMaxDynamicSharedMemorySize, MM_SMEM);
    cudaFuncSetAttribute(mm_gemm<EPI_EMB>,   cudaFuncAttributeMaxDynamicSharedMemorySize, MM_SMEM);

    instnorm_kernel<<<B_*CIN, 128>>>(x_enc);
    xcat_kernel<<<(NTOK*CIN)/256, 256>>>();
    wcat_kernel<<<(D_*96 + 255)/256, 256>>>(conv_w);
    mm_gemm<EPI_EMB><<<dim3(4,128), 256, MM_SMEM>>>(xcat, wcat, nullptr, h, NTOK, D_, 96);

    for (int i = 0; i < 3; ++i) {
        size_t WO = (size_t)i*D_*D_;
        mm_gemm<EPI_QKV><<<dim3(4,128), 256, MM_SMEM>>>(h, Wq+WO, bq+i*D_, q, NTOK, D_, D_);
        mm_gemm<EPI_QKV><<<dim3(4,128), 256, MM_SMEM>>>(h, Wk+WO, bk+i*D_, k, NTOK, D_, D_);
        mm_gemm<EPI_QKV><<<dim3(4,128), 256, MM_SMEM>>>(h, Wv+WO, bv+i*D_, v, NTOK, D_, D_);
        attn_kernel<<<dim3(8, B_*H_), 256, ATTN_SMEM>>>();
        mm_gemm<EPI_PLAIN><<<dim3(4,128), 256, MM_SMEM>>>(attn, Wo+WO, bo+i*D_, tmp, NTOK, D_, D_);
        add_ln_kernel<<<NTOK, 128>>>(h, tmp, n1_g+i*D_, n1_b+i*D_, x1);
        mm_gemm<EPI_GELU><<<dim3(16,128), 256, MM_SMEM>>>(x1, ff1_w+(size_t)i*DFF*D_, ff1_b+i*DFF, ff, NTOK, DFF, D_);
        mm_gemm<EPI_PLAIN><<<dim3(4,128), 256, MM_SMEM>>>(ff, ff2_w+(size_t)i*D_*DFF, ff2_b+i*D_, tmp, NTOK, D_, DFF);
        add_ln_kernel<<<NTOK, 128>>>(x1, tmp, n2_g+i*D_, n2_b+i*D_, h);
    }

    add_ln_kernel<<<NTOK, 128>>>(h, nullptr, fn_g, fn_b, h);
    gemm_f32<<<dim3(1,128), 256>>>(h, Wch, bch, dec1, NTOK, CIN, D_);
    timeproj_kernel<<<B_*PRED, 128>>>(Wt, bt, out);
}

// round 4
// speedup vs baseline: 6.2765x; 2.9205x over previous
#include <cuda_runtime.h>
#include <cuda_fp16.h>
#include <cstdint>
#include <math.h>

#define B_   32
#define SEQ  512
#define PRED 96
#define CIN  32
#define D_   512
#define H_   8
#define E_   64
#define DFF  2048
#define NTOK (B_*SEQ)   // 16384

// ---------------- fp32 scratch ----------------
__device__ float g_xn[B_*SEQ*CIN];
__device__ float g_mean[B_*CIN];
__device__ float g_std[B_*CIN];
__device__ float g_h[NTOK*D_];
__device__ float g_tmp[NTOK*D_];
__device__ float g_x1[NTOK*D_];
__device__ float g_dec1[NTOK*CIN];

// ---------------- fp16 scratch ----------------
__device__ __half g_h16[NTOK*D_];
__device__ __half g_x116[NTOK*D_];
__device__ __half g_attn16[NTOK*D_];
__device__ __half g_q16[NTOK*D_];
__device__ __half g_k16[NTOK*D_];
__device__ __half g_v16[NTOK*D_];
__device__ __half g_ff16[NTOK*DFF];
__device__ __half g_xcat16[NTOK*128];
__device__ __half g_wcat16[D_*128];

// converted weights: [Wq|Wk|Wv|Wo][ff1][ff2], 3 layers each
#define WOFF_WQ  0
#define WOFF_WK  786432
#define WOFF_WV  1572864
#define WOFF_WO  2359296
#define WOFF_F1  3145728
#define WOFF_F2  6291456
#define WTOT     9437184
__device__ __half g_w16[WTOT];

// ---------------- PTX helpers ----------------
__device__ __forceinline__ uint32_t smem_u32(const void* p) {
    uint32_t a;
    asm("{ .reg .u64 t; cvta.to.shared.u64 t, %1; cvt.u32.u64 %0, t; }" : "=r"(a) : "l"(p));
    return a;
}
__device__ __forceinline__ void cpasync16(uint32_t dst, const void* src) {
    asm volatile("cp.async.cg.shared.global [%0], [%1], 16;" :: "r"(dst), "l"(src));
}
__device__ __forceinline__ void cpcommit() {
    asm volatile("cp.async.commit_group;" ::: "memory");
}
#define CPWAIT(n) asm volatile("cp.async.wait_group %0;" :: "n"(n) : "memory")

__device__ __forceinline__ void ldsm4(uint32_t* r, uint32_t addr) {
    asm volatile("ldmatrix.sync.aligned.m8n8.x4.shared.b16 {%0,%1,%2,%3}, [%4];"
                 : "=r"(r[0]), "=r"(r[1]), "=r"(r[2]), "=r"(r[3]) : "r"(addr));
}
__device__ __forceinline__ void ldsm4t(uint32_t* r, uint32_t addr) {
    asm volatile("ldmatrix.sync.aligned.m8n8.x4.trans.shared.b16 {%0,%1,%2,%3}, [%4];"
                 : "=r"(r[0]), "=r"(r[1]), "=r"(r[2]), "=r"(r[3]) : "r"(addr));
}
__device__ __forceinline__ void mma16816(float* c, const uint32_t* a, const uint32_t* b) {
    asm volatile(
        "mma.sync.aligned.m16n8k16.row.col.f32.f16.f16.f32 "
        "{%0,%1,%2,%3}, {%4,%5,%6,%7}, {%8,%9}, {%0,%1,%2,%3};"
        : "+f"(c[0]), "+f"(c[1]), "+f"(c[2]), "+f"(c[3])
        : "r"(a[0]), "r"(a[1]), "r"(a[2]), "r"(a[3]), "r"(b[0]), "r"(b[1]));
}
__device__ __forceinline__ uint32_t packh2(float a, float b) {
    __half2 h = __floats2half2_rn(a, b);
    return *(uint32_t*)&h;
}

enum { EPI_PLAIN = 0, EPI_GELU = 1, EPI_QKV = 2, EPI_EMB = 3 };

// ============ fp16 mma GEMM: C[M,N] = A[M,K]*B[N,K]^T (+epilogue) ============
// M,N multiples of 128; K multiple of 64. A,B fp16 row-major.
// smem stage: A 128x64 halves (16KB, XOR-swizzled) + B same = 32KB; 3 stages.
#define HG_SMEM 98304

template<int EPI>
__global__ void __launch_bounds__(256, 2) hgemm(
    const __half* __restrict__ A, const __half* __restrict__ Bm,
    const float* __restrict__ bias, float* __restrict__ C32,
    __half* __restrict__ C16, int M, int N, int K)
{
    extern __shared__ __align__(16) char smem[];
    uint32_t sb = smem_u32(smem);
    const uint32_t STG = 32768u;
    int tid = threadIdx.x, lane = tid & 31, wid = tid >> 5;
    int g = lane >> 2, tg = lane & 3;
    int wm = wid & 1, wn = wid >> 1;         // warp tile: rows wm*64, cols wn*32
    int m0 = blockIdx.y * 128, n0 = blockIdx.x * 128;
    int nch = K >> 6;

    float acc[4][4][4];
    #pragma unroll
    for (int i = 0; i < 4; ++i)
        #pragma unroll
        for (int j = 0; j < 4; ++j)
            #pragma unroll
            for (int e = 0; e < 4; ++e) acc[i][j][e] = 0.f;

    auto issue = [&](int c) {
        uint32_t buf = sb + (uint32_t)(c % 3) * STG;
        const __half* Ag = A + (size_t)m0 * K + c * 64;
        const __half* Bg = Bm + (size_t)n0 * K + c * 64;
        #pragma unroll
        for (int u = 0; u < 4; ++u) {
            int slot = tid + 256 * u;            // 0..1023
            int r = slot >> 3, c16 = slot & 7;
            uint32_t off = (uint32_t)(r * 128) + (uint32_t)((c16 ^ (r & 7)) << 4);
            cpasync16(buf + off, Ag + (size_t)r * K + c16 * 8);
            cpasync16(buf + 16384u + off, Bg + (size_t)r * K + c16 * 8);
        }
        cpcommit();
    };

    issue(0); issue(1);
    for (int c = 0; c < nch; ++c) {
        if (c + 1 < nch) { CPWAIT(1); } else { CPWAIT(0); }
        __syncthreads();
        if (c + 2 < nch) issue(c + 2);
        uint32_t abase = sb + (uint32_t)(c % 3) * STG;
        uint32_t bbase = abase + 16384u;
        #pragma unroll
        for (int ks = 0; ks < 4; ++ks) {
            uint32_t af[4][4];
            #pragma unroll
            for (int mi = 0; mi < 4; ++mi) {
                int row = wm * 64 + mi * 16 + (lane & 15);
                int c16 = ks * 2 + (lane >> 4);
                ldsm4(af[mi], abase + (uint32_t)(row * 128) + (uint32_t)((c16 ^ (row & 7)) << 4));
            }
            uint32_t bf[2][4];
            #pragma unroll
            for (int ng = 0; ng < 2; ++ng) {
                int row = wn * 32 + ng * 16 + (lane & 7) + (((lane >> 4) & 1) << 3);
                int c16 = ks * 2 + ((lane >> 3) & 1);
                ldsm4(bf[ng], bbase + (uint32_t)(row * 128) + (uint32_t)((c16 ^ (row & 7)) << 4));
            }
            #pragma unroll
            for (int mi = 0; mi < 4; ++mi)
                #pragma unroll
                for (int ni = 0; ni < 4; ++ni)
                    mma16816(acc[mi][ni], af[mi], &bf[ni >> 1][(ni & 1) * 2]);
        }
    }

    // -------- epilogue --------
    #pragma unroll
    for (int mi = 0; mi < 4; ++mi) {
        #pragma unroll
        for (int rr = 0; rr < 2; ++rr) {
            int m = m0 + wm * 64 + mi * 16 + g + rr * 8;
            #pragma unroll
            for (int ni = 0; ni < 4; ++ni) {
                int n = n0 + wn * 32 + ni * 8 + tg * 2;
                float x0 = acc[mi][ni][rr * 2 + 0];
                float x1 = acc[mi][ni][rr * 2 + 1];
                if (EPI != EPI_EMB) {
                    float2 bv = *(const float2*)(bias + n);
                    x0 += bv.x; x1 += bv.y;
                }
                if (EPI == EPI_GELU) {
                    x0 = 0.5f * x0 * (1.0f + erff(x0 * 0.7071067811865475f));
                    x1 = 0.5f * x1 * (1.0f + erff(x1 * 0.7071067811865475f));
                    *(uint32_t*)(C16 + (size_t)m * N + n) = packh2(x0, x1);
                } else if (EPI == EPI_QKV) {
                    int bb2 = m >> 9, l = m & 511, hh = n >> 6, e = n & 63;
                    __half* op = C16 + (((size_t)(bb2 * H_ + hh)) * SEQ + l) * E_ + e;
                    *(uint32_t*)op = packh2(x0, x1);
                } else if (EPI == EPI_EMB) {
                    int l = m & (SEQ - 1);
                    float fr = expf(-(float)n * (9.210340371976184f / (float)D_)); // n even
                    float ang = (float)l * fr;
                    x0 += sinf(ang);
                    x1 += cosf(ang);
                    *(float2*)(C32 + (size_t)m * N + n) = make_float2(x0, x1);
                    *(uint32_t*)(C16 + (size_t)m * N + n) = packh2(x0, x1);
                } else {
                    *(float2*)(C32 + (size_t)m * N + n) = make_float2(x0, x1);
                }
            }
        }
    }
}

// ============ fp16 flash attention: q/k/v16 [B,H,S,E] -> attn16 [B,S,D] ============
// CTA: 256 thr (8 warps), q-tile 128 rows; keys streamed in 64-tiles, double-buffered.
#define AT_SMEM 49152
__global__ void __launch_bounds__(256) fattn() {
    extern __shared__ __align__(16) char smem[];
    uint32_t sb = smem_u32(smem);
    const uint32_t QOFF = 0, KOFF = 16384, VOFF = 32768; // K/V stages: +8192*(t&1)... K at KOFF+st*8192? K needs 2 stages of 8KB -> KOFF..KOFF+16KB, V same
    int tid = threadIdx.x, lane = tid & 31, wid = tid >> 5;
    int g = lane >> 2, tg = lane & 3;
    int bh = blockIdx.y, qt = blockIdx.x;
    const __half* qg = g_q16 + ((size_t)bh * SEQ + qt * 128) * E_;
    const __half* kg = g_k16 + (size_t)bh * SEQ * E_;
    const __half* vg = g_v16 + (size_t)bh * SEQ * E_;

    // Q tile: 128 rows x 64 halves
    #pragma unroll
    for (int u = 0; u < 4; ++u) {
        int slot = tid + 256 * u;
        int r = slot >> 3, c16 = slot & 7;
        uint32_t off = (uint32_t)(r * 128) + (uint32_t)((c16 ^ (r & 7)) << 4);
        cpasync16(sb + QOFF + off, qg + r * 64 + c16 * 8);
    }
    cpcommit();

    auto issueKV = [&](int t) {
        uint32_t kb = sb + KOFF + (uint32_t)(t & 1) * 8192u;
        uint32_t vb = sb + VOFF + (uint32_t)(t & 1) * 8192u;
        const __half* ks = kg + (size_t)t * 64 * E_;
        const __half* vs = vg + (size_t)t * 64 * E_;
        #pragma unroll
        for (int u = 0; u < 2; ++u) {
            int slot = tid + 256 * u;            // 0..511
            int r = slot >> 3, c16 = slot & 7;
            uint32_t off = (uint32_t)(r * 128) + (uint32_t)((c16 ^ (r & 7)) << 4);
            cpasync16(kb + off, ks + r * 64 + c16 * 8);
            cpasync16(vb + off, vs + r * 64 + c16 * 8);
        }
        cpcommit();
    };
    issueKV(0);

    CPWAIT(1);           // Q ready
    __syncthreads();
    uint32_t qf[4][4];
    #pragma unroll
    for (int ks = 0; ks < 4; ++ks) {
        int row = wid * 16 + (lane & 15);
        int c16 = ks * 2 + (lane >> 4);
        ldsm4(qf[ks], sb + QOFF + (uint32_t)(row * 128) + (uint32_t)((c16 ^ (row & 7)) << 4));
    }

    float oacc[8][4];
    #pragma unroll
    for (int i = 0; i < 8; ++i)
        #pragma unroll
        for (int e = 0; e < 4; ++e) oacc[i][e] = 0.f;
    float mrun[2] = {-1e30f, -1e30f}, lrun[2] = {0.f, 0.f};

    for (int t = 0; t < 8; ++t) {
        __syncthreads();                      // all warps done reading stage (t+1)&1 from iter t-1
        if (t + 1 < 8) { issueKV(t + 1); CPWAIT(1); } else { CPWAIT(0); }
        __syncthreads();                      // stage t data visible to all
        uint32_t kb = sb + KOFF + (uint32_t)(t & 1) * 8192u;
        uint32_t vb = sb + VOFF + (uint32_t)(t & 1) * 8192u;

        float sacc[8][4];
        #pragma unroll
        for (int i = 0; i < 8; ++i)
            #pragma unroll
            for (int e = 0; e < 4; ++e) sacc[i][e] = 0.f;

        #pragma unroll
        for (int ks = 0; ks < 4; ++ks) {
            #pragma unroll
            for (int ng = 0; ng < 4; ++ng) {
                int row = ng * 16 + (lane & 7) + (((lane >> 4) & 1) << 3);
                int c16 = ks * 2 + ((lane >> 3) & 1);
                uint32_t bf[4];
                ldsm4(bf, kb + (uint32_t)(row * 128) + (uint32_t)((c16 ^ (row & 7)) << 4));
                mma16816(sacc[ng * 2 + 0], qf[ks], &bf[0]);
                mma16816(sacc[ng * 2 + 1], qf[ks], &bf[2]);
            }
        }

        // online softmax (2 row-halves: rows g and g+8)
        uint32_t pf[8][2];
        #pragma unroll
        for (int h2 = 0; h2 < 2; ++h2) {
            float mt = -1e30f;
            #pragma unroll
            for (int nt = 0; nt < 8; ++nt)
                mt = fmaxf(mt, fmaxf(sacc[nt][h2 * 2], sacc[nt][h2 * 2 + 1]));
            mt = fmaxf(mt, __shfl_xor_sync(0xffffffffu, mt, 1));
            mt = fmaxf(mt, __shfl_xor_sync(0xffffffffu, mt, 2));
            float mnew = fmaxf(mrun[h2], mt);
            float al = __expf(0.125f * (mrun[h2] - mnew));
            lrun[h2] *= al;
            #pragma unroll
            for (int nt = 0; nt < 8; ++nt) { oacc[nt][h2 * 2] *= al; oacc[nt][h2 * 2 + 1] *= al; }
            float ps = 0.f;
            #pragma unroll
            for (int nt = 0; nt < 8; ++nt) {
                float p0 = __expf(0.125f * (sacc[nt][h2 * 2] - mnew));
                float p1 = __expf(0.125f * (sacc[nt][h2 * 2 + 1] - mnew));
                ps += p0 + p1;
                pf[nt][h2] = packh2(p0, p1);
            }
            ps += __shfl_xor_sync(0xffffffffu, ps, 1);
            ps += __shfl_xor_sync(0xffffffffu, ps, 2);
            lrun[h2] += ps;
            mrun[h2] = mnew;
        }

        // O += P @ V
        #pragma unroll
        for (int ks = 0; ks < 4; ++ks) {
            uint32_t af[4] = { pf[2 * ks][0], pf[2 * ks][1], pf[2 * ks + 1][0], pf[2 * ks + 1][1] };
            #pragma unroll
            for (int eg = 0; eg < 4; ++eg) {
                int row = ks * 16 + (lane & 7) + (((lane >> 3) & 1) << 3);
                int c16 = eg * 2 + (lane >> 4);
                uint32_t bf[4];
                ldsm4t(bf, vb + (uint32_t)(row * 128) + (uint32_t)((c16 ^ (row & 7)) << 4));
                mma16816(oacc[eg * 2 + 0], af, &bf[0]);
                mma16816(oacc[eg * 2 + 1], af, &bf[2]);
            }
        }
    }

    int b = bh >> 3, hh = bh & 7;
    #pragma unroll
    for (int h2 = 0; h2 < 2; ++h2) {
        float inv = 1.0f / lrun[h2];
        int l = qt * 128 + wid * 16 + g + 8 * h2;
        __half* op = g_attn16 + ((size_t)(b * SEQ + l)) * D_ + hh * 64;
        #pragma unroll
        for (int nt = 0; nt < 8; ++nt) {
            int e = nt * 8 + tg * 2;
            *(uint32_t*)(op + e) = packh2(oacc[nt][h2 * 2] * inv, oacc[nt][h2 * 2 + 1] * inv);
        }
    }
}

// ---------------- weight conversion (fp32 -> fp16), one pass ----------------
__global__ void convert_weights(const float* __restrict__ Wq, const float* __restrict__ Wk,
                                const float* __restrict__ Wv, const float* __restrict__ Wo,
                                const float* __restrict__ F1, const float* __restrict__ F2)
{
    size_t i4 = ((size_t)blockIdx.x * 256 + threadIdx.x) * 4;
    if (i4 >= WTOT) return;
    const float* src;
    size_t off;
    if      (i4 < WOFF_WK) { src = Wq; off = i4 - WOFF_WQ; }
    else if (i4 < WOFF_WV) { src = Wk; off = i4 - WOFF_WK; }
    else if (i4 < WOFF_WO) { src = Wv; off = i4 - WOFF_WV; }
    else if (i4 < WOFF_F1) { src = Wo; off = i4 - WOFF_WO; }
    else if (i4 < WOFF_F2) { src = F1; off = i4 - WOFF_F1; }
    else                   { src = F2; off = i4 - WOFF_F2; }
    float4 v = *(const float4*)(src + off);
    uint32_t lo = packh2(v.x, v.y), hi = packh2(v.z, v.w);
    *(uint2*)(g_w16 + i4) = make_uint2(lo, hi);
}

// ---------------- helpers ----------------
__device__ __forceinline__ float blockSum128(float v, float* sbuf) {
    #pragma unroll
    for (int o = 16; o; o >>= 1) v += __shfl_xor_sync(0xffffffffu, v, o);
    int w = threadIdx.x >> 5;
    if ((threadIdx.x & 31) == 0) sbuf[w] = v;
    __syncthreads();
    v = sbuf[0] + sbuf[1] + sbuf[2] + sbuf[3];
    __syncthreads();
    return v;
}

// ---------------- instance norm over time, per (b,c) ----------------
__global__ void instnorm_kernel(const float* __restrict__ x) {
    __shared__ float sbuf[4];
    int b = blockIdx.x >> 5, c = blockIdx.x & 31;
    int t = threadIdx.x;
    float v[4];
    #pragma unroll
    for (int u = 0; u < 4; ++u)
        v[u] = x[((size_t)b*SEQ + t + 128*u)*CIN + c];
    float s = v[0]+v[1]+v[2]+v[3];
    s = blockSum128(s, sbuf);
    float mean = s * (1.0f/SEQ);
    float qq = 0.f;
    #pragma unroll
    for (int u = 0; u < 4; ++u) { float d = v[u]-mean; qq += d*d; }
    qq = blockSum128(qq, sbuf);
    float sd = sqrtf(qq*(1.0f/SEQ) + 1e-5f);
    float inv = 1.0f/sd;
    #pragma unroll
    for (int u = 0; u < 4; ++u)
        g_xn[((size_t)b*SEQ + t + 128*u)*CIN + c] = (v[u]-mean)*inv;
    if (t == 0) { g_mean[b*CIN+c] = mean; g_std[b*CIN+c] = sd; }
}

// ---------------- build circular-conv input matrix [NTOK, 128] fp16 (zero-padded) ----------------
__global__ void xcat16_kernel() {
    int idx = blockIdx.x*256 + threadIdx.x;   // NTOK*128
    if (idx >= NTOK*128) return;
    int r = idx & 127, n = idx >> 7;
    float val = 0.f;
    if (r < 96) {
        int kk = r >> 5, c = r & 31;
        int b = n >> 9, l = n & 511;
        int ls = (l + kk - 1 + SEQ) & (SEQ-1);
        val = g_xn[((size_t)b*SEQ + ls)*CIN + c];
    }
    g_xcat16[idx] = __float2half_rn(val);
}

__global__ void wcat16_kernel(const float* __restrict__ cw) {
    int idx = blockIdx.x*256 + threadIdx.x;   // D_*128
    if (idx >= D_*128) return;
    int r = idx & 127, d = idx >> 7;
    float val = 0.f;
    if (r < 96) {
        int kk = r >> 5, c = r & 31;
        val = cw[(d*CIN + c)*3 + kk];
    }
    g_wcat16[idx] = __float2half_rn(val);
}

// ---------------- fp32 SGEMM (tiny final channel projection) ----------------
__global__ void __launch_bounds__(256, 2) gemm_f32(
    const float* __restrict__ A, const float* __restrict__ Bm,
    const float* __restrict__ bias, float* __restrict__ C,
    int M, int N, int K)
{
    __shared__ float As[16][132];
    __shared__ float Bs[16][132];
    int tid = threadIdx.x;
    int m0 = blockIdx.y * 128, n0 = blockIdx.x * 128;
    int tx = tid & 15, ty = tid >> 4;
    int lr = tid >> 2;
    int lq = (tid & 3) * 4;

    float acc[8][8];
    #pragma unroll
    for (int i = 0; i < 8; ++i)
        #pragma unroll
        for (int j = 0; j < 8; ++j) acc[i][j] = 0.f;

    for (int k0 = 0; k0 < K; k0 += 16) {
        #pragma unroll
        for (int hh = 0; hh < 2; ++hh) {
            int r = lr + hh*64;
            int gm = m0 + r;
            float4 va = make_float4(0.f,0.f,0.f,0.f);
            if (gm < M) va = *(const float4*)(A + (size_t)gm*K + k0 + lq);
            As[lq+0][r] = va.x; As[lq+1][r] = va.y; As[lq+2][r] = va.z; As[lq+3][r] = va.w;
            int gn = n0 + r;
            float4 vb = make_float4(0.f,0.f,0.f,0.f);
            if (gn < N) vb = *(const float4*)(Bm + (size_t)gn*K + k0 + lq);
            Bs[lq+0][r] = vb.x; Bs[lq+1][r] = vb.y; Bs[lq+2][r] = vb.z; Bs[lq+3][r] = vb.w;
        }
        __syncthreads();
        #pragma unroll
        for (int kk = 0; kk < 16; ++kk) {
            float4 a0 = *(const float4*)(&As[kk][ty*4]);
            float4 a1 = *(const float4*)(&As[kk][64 + ty*4]);
            float4 b0 = *(const float4*)(&Bs[kk][tx*4]);
            float4 b1 = *(const float4*)(&Bs[kk][64 + tx*4]);
            float av[8] = {a0.x,a0.y,a0.z,a0.w,a1.x,a1.y,a1.z,a1.w};
            float bv[8] = {b0.x,b0.y,b0.z,b0.w,b1.x,b1.y,b1.z,b1.w};
            #pragma unroll
            for (int i = 0; i < 8; ++i)
                #pragma unroll
                for (int j = 0; j < 8; ++j)
                    acc[i][j] = fmaf(av[i], bv[j], acc[i][j]);
        }
        __syncthreads();
    }

    #pragma unroll
    for (int i = 0; i < 8; ++i) {
        int mi = (i < 4) ? (ty*4 + i) : (64 + ty*4 + i - 4);
        int m = m0 + mi;
        if (m >= M) continue;
        #pragma unroll
        for (int j = 0; j < 8; ++j) {
            int nj = (j < 4) ? (tx*4 + j) : (64 + tx*4 + j - 4);
            int n = n0 + nj;
            if (n >= N) continue;
            C[(size_t)m*N + n] = acc[i][j] + bias[n];
        }
    }
}

// ---------------- fused (optional residual add) + LayerNorm + fp16 copy ----------------
__global__ void add_ln_kernel(const float* __restrict__ A, const float* __restrict__ R,
                              const float* __restrict__ g, const float* __restrict__ be,
                              float* __restrict__ out, __half* __restrict__ out16)
{
    __shared__ float sbuf[4];
    size_t n = blockIdx.x;
    int t = threadIdx.x;
    float4 v = ((const float4*)(A + n*D_))[t];
    if (R) {
        float4 r = ((const float4*)(R + n*D_))[t];
        v.x += r.x; v.y += r.y; v.z += r.z; v.w += r.w;
    }
    float s = v.x + v.y + v.z + v.w;
    s = blockSum128(s, sbuf);
    float mean = s * (1.0f/D_);
    float dx = v.x-mean, dy = v.y-mean, dz = v.z-mean, dw = v.w-mean;
    float qq = dx*dx + dy*dy + dz*dz + dw*dw;
    qq = blockSum128(qq, sbuf);
    float rstd = rsqrtf(qq*(1.0f/D_) + 1e-5f);
    float4 gv = ((const float4*)g)[t];
    float4 bv = ((const float4*)be)[t];
    float4 o;
    o.x = dx*rstd*gv.x + bv.x;
    o.y = dy*rstd*gv.y + bv.y;
    o.z = dz*rstd*gv.z + bv.z;
    o.w = dw*rstd*gv.w + bv.w;
    ((float4*)(out + n*D_))[t] = o;
    if (out16) {
        uint2 h;
        h.x = packh2(o.x, o.y);
        h.y = packh2(o.z, o.w);
        ((uint2*)(out16 + n*D_))[t] = h;
    }
}

// ---------------- time projection + de-normalization ----------------
__global__ void timeproj_kernel(const float* __restrict__ Wt, const float* __restrict__ bt,
                                float* __restrict__ out)
{
    __shared__ float sw[512];
    __shared__ float sred[4][32];
    int bp = blockIdx.x;
    int b = bp / PRED, p = bp % PRED;
    int t = threadIdx.x;
    for (int j = t; j < 512; j += 128) sw[j] = Wt[p*512 + j];
    __syncthreads();
    int c = t & 31, part = t >> 5;
    const float* dp = g_dec1 + (size_t)b*SEQ*CIN;
    float s = 0.f;
    for (int l = part*128; l < part*128 + 128; ++l)
        s += dp[l*CIN + c] * sw[l];
    sred[part][c] = s;
    __syncthreads();
    if (t < 32) {
        float tot = sred[0][c] + sred[1][c] + sred[2][c] + sred[3][c] + bt[p];
        out[((size_t)b*PRED + p)*CIN + c] = tot * g_std[b*CIN+c] + g_mean[b*CIN+c];
    }
}

// ---------------- launch ----------------
extern "C" void kernel_launch(void* const* d_in, const int* in_sizes, int n_in,
                              void* d_out, int out_size)
{
    const float* x_enc  = (const float*)d_in[0];
    const float* conv_w = (const float*)d_in[1];
    const float* Wq = (const float*)d_in[2];
    const float* Wk = (const float*)d_in[3];
    const float* Wv = (const float*)d_in[4];
    const float* Wo = (const float*)d_in[5];
    const float* bq = (const float*)d_in[6];
    const float* bk = (const float*)d_in[7];
    const float* bv = (const float*)d_in[8];
    const float* bo = (const float*)d_in[9];
    const float* ff1_w = (const float*)d_in[10];
    const float* ff1_b = (const float*)d_in[11];
    const float* ff2_w = (const float*)d_in[12];
    const float* ff2_b = (const float*)d_in[13];
    const float* n1_g = (const float*)d_in[14];
    const float* n1_b = (const float*)d_in[15];
    const float* n2_g = (const float*)d_in[16];
    const float* n2_b = (const float*)d_in[17];
    const float* fn_g = (const float*)d_in[18];
    const float* fn_b = (const float*)d_in[19];
    const float* Wch  = (const float*)d_in[20];
    const float* bch  = (const float*)d_in[21];
    const float* Wt   = (const float*)d_in[22];
    const float* bt   = (const float*)d_in[23];
    float* out = (float*)d_out;

    float *h, *tmp, *x1, *dec1;
    __half *h16, *x116, *attn16, *q16, *k16, *v16, *ff16, *xcat16, *wcat16, *w16;
    cudaGetSymbolAddress((void**)&h,    g_h);
    cudaGetSymbolAddress((void**)&tmp,  g_tmp);
    cudaGetSymbolAddress((void**)&x1,   g_x1);
    cudaGetSymbolAddress((void**)&dec1, g_dec1);
    cudaGetSymbolAddress((void**)&h16,    g_h16);
    cudaGetSymbolAddress((void**)&x116,   g_x116);
    cudaGetSymbolAddress((void**)&attn16, g_attn16);
    cudaGetSymbolAddress((void**)&q16,    g_q16);
    cudaGetSymbolAddress((void**)&k16,    g_k16);
    cudaGetSymbolAddress((void**)&v16,    g_v16);
    cudaGetSymbolAddress((void**)&ff16,   g_ff16);
    cudaGetSymbolAddress((void**)&xcat16, g_xcat16);
    cudaGetSymbolAddress((void**)&wcat16, g_wcat16);
    cudaGetSymbolAddress((void**)&w16,    g_w16);

    cudaFuncSetAttribute(hgemm<EPI_PLAIN>, cudaFuncAttributeMaxDynamicSharedMemorySize, HG_SMEM);
    cudaFuncSetAttribute(hgemm<EPI_GELU>,  cudaFuncAttributeMaxDynamicSharedMemorySize, HG_SMEM);
    cudaFuncSetAttribute(hgemm<EPI_QKV>,   cudaFuncAttributeMaxDynamicSharedMemorySize, HG_SMEM);
    cudaFuncSetAttribute(hgemm<EPI_EMB>,   cudaFuncAttributeMaxDynamicSharedMemorySize, HG_SMEM);
    cudaFuncSetAttribute(fattn, cudaFuncAttributeMaxDynamicSharedMemorySize, AT_SMEM);

    convert_weights<<<(WTOT/4 + 255)/256, 256>>>(Wq, Wk, Wv, Wo, ff1_w, ff2_w);
    instnorm_kernel<<<B_*CIN, 128>>>(x_enc);
    xcat16_kernel<<<(NTOK*128)/256, 256>>>();
    wcat16_kernel<<<(D_*128)/256, 256>>>(conv_w);
    hgemm<EPI_EMB><<<dim3(4,128), 256, HG_SMEM>>>(xcat16, wcat16, nullptr, h, h16, NTOK, D_, 128);

    for (int i = 0; i < 3; ++i) {
        size_t WO = (size_t)i*D_*D_;
        hgemm<EPI_QKV><<<dim3(4,128), 256, HG_SMEM>>>(h16, w16+WOFF_WQ+WO, bq+i*D_, nullptr, q16, NTOK, D_, D_);
        hgemm<EPI_QKV><<<dim3(4,128), 256, HG_SMEM>>>(h16, w16+WOFF_WK+WO, bk+i*D_, nullptr, k16, NTOK, D_, D_);
        hgemm<EPI_QKV><<<dim3(4,128), 256, HG_SMEM>>>(h16, w16+WOFF_WV+WO, bv+i*D_, nullptr, v16, NTOK, D_, D_);
        fattn<<<dim3(4, B_*H_), 256, AT_SMEM>>>();
        hgemm<EPI_PLAIN><<<dim3(4,128), 256, HG_SMEM>>>(attn16, w16+WOFF_WO+WO, bo+i*D_, tmp, nullptr, NTOK, D_, D_);
        add_ln_kernel<<<NTOK, 128>>>(h, tmp, n1_g+i*D_, n1_b+i*D_, x1, x116);
        hgemm<EPI_GELU><<<dim3(16,128), 256, HG_SMEM>>>(x116, w16+WOFF_F1+(size_t)i*DFF*D_, ff1_b+i*DFF, nullptr, ff16, NTOK, DFF, D_);
        hgemm<EPI_PLAIN><<<dim3(4,128), 256, HG_SMEM>>>(ff16, w16+WOFF_F2+(size_t)i*D_*DFF, ff2_b+i*D_, tmp, nullptr, NTOK, D_, DFF);
        add_ln_kernel<<<NTOK, 128>>>(x1, tmp, n2_g+i*D_, n2_b+i*D_, h, h16);
    }

    add_ln_kernel<<<NTOK, 128>>>(h, nullptr, fn_g, fn_b, h, nullptr);
    gemm_f32<<<dim3(1,128), 256>>>(h, Wch, bch, dec1, NTOK, CIN, D_);
    timeproj_kernel<<<B_*PRED, 128>>>(Wt, bt, out);
}

// round 5
// speedup vs baseline: 6.3333x; 1.0091x over previous
#include <cuda_runtime.h>
#include <cuda_fp16.h>
#include <cstdint>
#include <math.h>

#define B_   32
#define SEQ  512
#define PRED 96
#define CIN  32
#define D_   512
#define H_   8
#define E_   64
#define DFF  2048
#define NTOK (B_*SEQ)   // 16384

// ---------------- fp32 scratch ----------------
__device__ float g_mean[B_*CIN];
__device__ float g_std[B_*CIN];
__device__ float g_h[NTOK*D_];
__device__ float g_tmp[NTOK*D_];
__device__ float g_x1[NTOK*D_];
__device__ float g_dec1[NTOK*CIN];
__device__ float g_bqkv[3*1536];

// ---------------- fp16 scratch ----------------
__device__ __half g_h16[NTOK*D_];
__device__ __half g_x116[NTOK*D_];
__device__ __half g_attn16[NTOK*D_];
__device__ __half g_q16[NTOK*D_];
__device__ __half g_k16[NTOK*D_];
__device__ __half g_v16[NTOK*D_];
__device__ __half g_ff16[NTOK*DFF];
__device__ __half g_xcat16[NTOK*128];
__device__ __half g_wcat16[D_*128];

// converted weights: [Wqkv(concat 1536x512 per layer)][Wo][ff1][ff2]
#define WOFF_QKV 0
#define WOFF_WO  2359296
#define WOFF_F1  3145728
#define WOFF_F2  6291456
#define WTOT     9437184
__device__ __half g_w16[WTOT];

// ---------------- PTX helpers ----------------
__device__ __forceinline__ uint32_t smem_u32(const void* p) {
    uint32_t a;
    asm("{ .reg .u64 t; cvta.to.shared.u64 t, %1; cvt.u32.u64 %0, t; }" : "=r"(a) : "l"(p));
    return a;
}
__device__ __forceinline__ void cpasync16(uint32_t dst, const void* src) {
    asm volatile("cp.async.cg.shared.global [%0], [%1], 16;" :: "r"(dst), "l"(src));
}
__device__ __forceinline__ void cpcommit() {
    asm volatile("cp.async.commit_group;" ::: "memory");
}
#define CPWAIT(n) asm volatile("cp.async.wait_group %0;" :: "n"(n) : "memory")

__device__ __forceinline__ void ldsm4(uint32_t* r, uint32_t addr) {
    asm volatile("ldmatrix.sync.aligned.m8n8.x4.shared.b16 {%0,%1,%2,%3}, [%4];"
                 : "=r"(r[0]), "=r"(r[1]), "=r"(r[2]), "=r"(r[3]) : "r"(addr));
}
__device__ __forceinline__ void ldsm4t(uint32_t* r, uint32_t addr) {
    asm volatile("ldmatrix.sync.aligned.m8n8.x4.trans.shared.b16 {%0,%1,%2,%3}, [%4];"
                 : "=r"(r[0]), "=r"(r[1]), "=r"(r[2]), "=r"(r[3]) : "r"(addr));
}
__device__ __forceinline__ void mma16816(float* c, const uint32_t* a, const uint32_t* b) {
    asm volatile(
        "mma.sync.aligned.m16n8k16.row.col.f32.f16.f16.f32 "
        "{%0,%1,%2,%3}, {%4,%5,%6,%7}, {%8,%9}, {%0,%1,%2,%3};"
        : "+f"(c[0]), "+f"(c[1]), "+f"(c[2]), "+f"(c[3])
        : "r"(a[0]), "r"(a[1]), "r"(a[2]), "r"(a[3]), "r"(b[0]), "r"(b[1]));
}
__device__ __forceinline__ uint32_t packh2(float a, float b) {
    __half2 h = __floats2half2_rn(a, b);
    return *(uint32_t*)&h;
}

enum { EPI_PLAIN = 0, EPI_GELU = 1, EPI_QKV = 2, EPI_EMB = 3 };

// ============ fp16 mma GEMM: C[M,N] = A[M,K]*B[N,K]^T (+epilogue) ============
#define HG_SMEM 98304

template<int EPI>
__global__ void __launch_bounds__(256, 2) hgemm(
    const __half* __restrict__ A, const __half* __restrict__ Bm,
    const float* __restrict__ bias, float* __restrict__ C32,
    __half* __restrict__ C16, int M, int N, int K)
{
    extern __shared__ __align__(16) char smem[];
    uint32_t sb = smem_u32(smem);
    const uint32_t STG = 32768u;
    int tid = threadIdx.x, lane = tid & 31, wid = tid >> 5;
    int g = lane >> 2, tg = lane & 3;
    int wm = wid & 1, wn = wid >> 1;
    int m0 = blockIdx.y * 128, n0 = blockIdx.x * 128;
    int nch = K >> 6;

    float acc[4][4][4];
    #pragma unroll
    for (int i = 0; i < 4; ++i)
        #pragma unroll
        for (int j = 0; j < 4; ++j)
            #pragma unroll
            for (int e = 0; e < 4; ++e) acc[i][j][e] = 0.f;

    auto issue = [&](int c) {
        uint32_t buf = sb + (uint32_t)(c % 3) * STG;
        const __half* Ag = A + (size_t)m0 * K + c * 64;
        const __half* Bg = Bm + (size_t)n0 * K + c * 64;
        #pragma unroll
        for (int u = 0; u < 4; ++u) {
            int slot = tid + 256 * u;
            int r = slot >> 3, c16 = slot & 7;
            uint32_t off = (uint32_t)(r * 128) + (uint32_t)((c16 ^ (r & 7)) << 4);
            cpasync16(buf + off, Ag + (size_t)r * K + c16 * 8);
            cpasync16(buf + 16384u + off, Bg + (size_t)r * K + c16 * 8);
        }
        cpcommit();
    };

    issue(0); issue(1);
    for (int c = 0; c < nch; ++c) {
        if (c + 1 < nch) { CPWAIT(1); } else { CPWAIT(0); }
        __syncthreads();
        if (c + 2 < nch) issue(c + 2);
        uint32_t abase = sb + (uint32_t)(c % 3) * STG;
        uint32_t bbase = abase + 16384u;
        #pragma unroll
        for (int ks = 0; ks < 4; ++ks) {
            uint32_t af[4][4];
            #pragma unroll
            for (int mi = 0; mi < 4; ++mi) {
                int row = wm * 64 + mi * 16 + (lane & 15);
                int c16 = ks * 2 + (lane >> 4);
                ldsm4(af[mi], abase + (uint32_t)(row * 128) + (uint32_t)((c16 ^ (row & 7)) << 4));
            }
            uint32_t bf[2][4];
            #pragma unroll
            for (int ng = 0; ng < 2; ++ng) {
                int row = wn * 32 + ng * 16 + (lane & 7) + (((lane >> 4) & 1) << 3);
                int c16 = ks * 2 + ((lane >> 3) & 1);
                ldsm4(bf[ng], bbase + (uint32_t)(row * 128) + (uint32_t)((c16 ^ (row & 7)) << 4));
            }
            #pragma unroll
            for (int mi = 0; mi < 4; ++mi)
                #pragma unroll
                for (int ni = 0; ni < 4; ++ni)
                    mma16816(acc[mi][ni], af[mi], &bf[ni >> 1][(ni & 1) * 2]);
        }
    }

    // -------- epilogue --------
    #pragma unroll
    for (int mi = 0; mi < 4; ++mi) {
        #pragma unroll
        for (int rr = 0; rr < 2; ++rr) {
            int m = m0 + wm * 64 + mi * 16 + g + rr * 8;
            #pragma unroll
            for (int ni = 0; ni < 4; ++ni) {
                int n = n0 + wn * 32 + ni * 8 + tg * 2;
                float x0 = acc[mi][ni][rr * 2 + 0];
                float x1 = acc[mi][ni][rr * 2 + 1];
                if (EPI != EPI_EMB) {
                    float2 bv = *(const float2*)(bias + n);
                    x0 += bv.x; x1 += bv.y;
                }
                if (EPI == EPI_GELU) {
                    x0 = 0.5f * x0 * (1.0f + erff(x0 * 0.7071067811865475f));
                    x1 = 0.5f * x1 * (1.0f + erff(x1 * 0.7071067811865475f));
                    *(uint32_t*)(C16 + (size_t)m * N + n) = packh2(x0, x1);
                } else if (EPI == EPI_QKV) {
                    // n in [0,1536): type = n>>9, d = n&511
                    int ty2 = n >> 9, d = n & 511;
                    int bb2 = m >> 9, l = m & 511, hh = d >> 6, e = d & 63;
                    __half* base = (ty2 == 0) ? g_q16 : (ty2 == 1) ? g_k16 : g_v16;
                    __half* op = base + (((size_t)(bb2 * H_ + hh)) * SEQ + l) * E_ + e;
                    *(uint32_t*)op = packh2(x0, x1);
                } else if (EPI == EPI_EMB) {
                    int l = m & (SEQ - 1);
                    float fr = expf(-(float)n * (9.210340371976184f / (float)D_)); // n even
                    float ang = (float)l * fr;
                    x0 += sinf(ang);
                    x1 += cosf(ang);
                    *(float2*)(C32 + (size_t)m * N + n) = make_float2(x0, x1);
                    *(uint32_t*)(C16 + (size_t)m * N + n) = packh2(x0, x1);
                } else {
                    *(float2*)(C32 + (size_t)m * N + n) = make_float2(x0, x1);
                }
            }
        }
    }
}

// ============ fp16 flash attention (3-stage KV ring, 1 sync/tile) ============
#define AT_SMEM 65536
__global__ void __launch_bounds__(256) fattn() {
    extern __shared__ __align__(16) char smem[];
    uint32_t sb = smem_u32(smem);
    int tid = threadIdx.x, lane = tid & 31, wid = tid >> 5;
    int g = lane >> 2, tg = lane & 3;
    int bh = blockIdx.y, qt = blockIdx.x;
    const __half* qg = g_q16 + ((size_t)bh * SEQ + qt * 128) * E_;
    const __half* kg = g_k16 + (size_t)bh * SEQ * E_;
    const __half* vg = g_v16 + (size_t)bh * SEQ * E_;

    // Q tile: 128 x 64 halves at offset 0 (16KB)
    #pragma unroll
    for (int u = 0; u < 4; ++u) {
        int slot = tid + 256 * u;
        int r = slot >> 3, c16 = slot & 7;
        uint32_t off = (uint32_t)(r * 128) + (uint32_t)((c16 ^ (r & 7)) << 4);
        cpasync16(sb + off, qg + r * 64 + c16 * 8);
    }
    cpcommit();

    auto issueKV = [&](int t) {
        uint32_t kb = sb + 16384u + (uint32_t)(t % 3) * 16384u;
        uint32_t vb = kb + 8192u;
        const __half* ks = kg + (size_t)t * 64 * E_;
        const __half* vs = vg + (size_t)t * 64 * E_;
        #pragma unroll
        for (int u = 0; u < 2; ++u) {
            int slot = tid + 256 * u;
            int r = slot >> 3, c16 = slot & 7;
            uint32_t off = (uint32_t)(r * 128) + (uint32_t)((c16 ^ (r & 7)) << 4);
            cpasync16(kb + off, ks + r * 64 + c16 * 8);
            cpasync16(vb + off, vs + r * 64 + c16 * 8);
        }
        cpcommit();
    };
    issueKV(0); issueKV(1);

    CPWAIT(2);               // Q ready (KV0,KV1 may be pending)
    __syncthreads();
    uint32_t qf[4][4];
    #pragma unroll
    for (int ks = 0; ks < 4; ++ks) {
        int row = wid * 16 + (lane & 15);
        int c16 = ks * 2 + (lane >> 4);
        ldsm4(qf[ks], sb + (uint32_t)(row * 128) + (uint32_t)((c16 ^ (row & 7)) << 4));
    }

    float oacc[8][4];
    #pragma unroll
    for (int i = 0; i < 8; ++i)
        #pragma unroll
        for (int e = 0; e < 4; ++e) oacc[i][e] = 0.f;
    float mrun[2] = {-1e30f, -1e30f}, lrun[2] = {0.f, 0.f};

    #pragma unroll
    for (int t = 0; t < 8; ++t) {
        if (t < 7) { CPWAIT(1); } else { CPWAIT(0); }
        __syncthreads();      // stage-t visible to all; all warps done with stage (t+2)%3
        if (t + 2 < 8) issueKV(t + 2);
        uint32_t kb = sb + 16384u + (uint32_t)(t % 3) * 16384u;
        uint32_t vb = kb + 8192u;

        float sacc[8][4];
        #pragma unroll
        for (int i = 0; i < 8; ++i)
            #pragma unroll
            for (int e = 0; e < 4; ++e) sacc[i][e] = 0.f;

        #pragma unroll
        for (int ks = 0; ks < 4; ++ks) {
            #pragma unroll
            for (int ng = 0; ng < 4; ++ng) {
                int row = ng * 16 + (lane & 7) + (((lane >> 4) & 1) << 3);
                int c16 = ks * 2 + ((lane >> 3) & 1);
                uint32_t bf[4];
                ldsm4(bf, kb + (uint32_t)(row * 128) + (uint32_t)((c16 ^ (row & 7)) << 4));
                mma16816(sacc[ng * 2 + 0], qf[ks], &bf[0]);
                mma16816(sacc[ng * 2 + 1], qf[ks], &bf[2]);
            }
        }

        uint32_t pf[8][2];
        #pragma unroll
        for (int h2 = 0; h2 < 2; ++h2) {
            float mt = -1e30f;
            #pragma unroll
            for (int nt = 0; nt < 8; ++nt)
                mt = fmaxf(mt, fmaxf(sacc[nt][h2 * 2], sacc[nt][h2 * 2 + 1]));
            mt = fmaxf(mt, __shfl_xor_sync(0xffffffffu, mt, 1));
            mt = fmaxf(mt, __shfl_xor_sync(0xffffffffu, mt, 2));
            float mnew = fmaxf(mrun[h2], mt);
            float al = __expf(0.125f * (mrun[h2] - mnew));
            lrun[h2] *= al;
            #pragma unroll
            for (int nt = 0; nt < 8; ++nt) { oacc[nt][h2 * 2] *= al; oacc[nt][h2 * 2 + 1] *= al; }
            float ps = 0.f;
            #pragma unroll
            for (int nt = 0; nt < 8; ++nt) {
                float p0 = __expf(0.125f * (sacc[nt][h2 * 2] - mnew));
                float p1 = __expf(0.125f * (sacc[nt][h2 * 2 + 1] - mnew));
                ps += p0 + p1;
                pf[nt][h2] = packh2(p0, p1);
            }
            ps += __shfl_xor_sync(0xffffffffu, ps, 1);
            ps += __shfl_xor_sync(0xffffffffu, ps, 2);
            lrun[h2] += ps;
            mrun[h2] = mnew;
        }

        #pragma unroll
        for (int ks = 0; ks < 4; ++ks) {
            uint32_t af[4] = { pf[2 * ks][0], pf[2 * ks][1], pf[2 * ks + 1][0], pf[2 * ks + 1][1] };
            #pragma unroll
            for (int eg = 0; eg < 4; ++eg) {
                int row = ks * 16 + (lane & 7) + (((lane >> 3) & 1) << 3);
                int c16 = eg * 2 + (lane >> 4);
                uint32_t bf[4];
                ldsm4t(bf, vb + (uint32_t)(row * 128) + (uint32_t)((c16 ^ (row & 7)) << 4));
                mma16816(oacc[eg * 2 + 0], af, &bf[0]);
                mma16816(oacc[eg * 2 + 1], af, &bf[2]);
            }
        }
    }

    int b = bh >> 3, hh = bh & 7;
    #pragma unroll
    for (int h2 = 0; h2 < 2; ++h2) {
        float inv = 1.0f / lrun[h2];
        int l = qt * 128 + wid * 16 + g + 8 * h2;
        __half* op = g_attn16 + ((size_t)(b * SEQ + l)) * D_ + hh * 64;
        #pragma unroll
        for (int nt = 0; nt < 8; ++nt) {
            int e = nt * 8 + tg * 2;
            *(uint32_t*)(op + e) = packh2(oacc[nt][h2 * 2] * inv, oacc[nt][h2 * 2 + 1] * inv);
        }
    }
}

// ---------------- weight conversion (fp32 -> fp16), QKV concatenated ----------------
__global__ void convert_weights(const float* __restrict__ Wq, const float* __restrict__ Wk,
                                const float* __restrict__ Wv, const float* __restrict__ Wo,
                                const float* __restrict__ F1, const float* __restrict__ F2)
{
    size_t i4 = ((size_t)blockIdx.x * 256 + threadIdx.x) * 4;
    if (i4 >= WTOT) return;
    const float* src;
    size_t off;
    if (i4 < WOFF_WO) {
        size_t layer = i4 / 786432, rem = i4 % 786432;
        size_t blk = rem / 262144;
        src = (blk == 0) ? Wq : (blk == 1) ? Wk : Wv;
        off = layer * 262144 + rem % 262144;
    }
    else if (i4 < WOFF_F1) { src = Wo; off = i4 - WOFF_WO; }
    else if (i4 < WOFF_F2) { src = F1; off = i4 - WOFF_F1; }
    else                   { src = F2; off = i4 - WOFF_F2; }
    float4 v = *(const float4*)(src + off);
    *(uint2*)(g_w16 + i4) = make_uint2(packh2(v.x, v.y), packh2(v.z, v.w));
}

__global__ void biascat_kernel(const float* __restrict__ bq, const float* __restrict__ bk,
                               const float* __restrict__ bv)
{
    int idx = blockIdx.x * 256 + threadIdx.x;
    if (idx >= 3 * 1536) return;
    int layer = idx / 1536, r = idx % 1536;
    int blk = r >> 9, d = r & 511;
    const float* src = (blk == 0) ? bq : (blk == 1) ? bk : bv;
    g_bqkv[idx] = src[layer * 512 + d];
}

// ---------------- helpers ----------------
__device__ __forceinline__ float blockSum128(float v, float* sbuf) {
    #pragma unroll
    for (int o = 16; o; o >>= 1) v += __shfl_xor_sync(0xffffffffu, v, o);
    int w = threadIdx.x >> 5;
    if ((threadIdx.x & 31) == 0) sbuf[w] = v;
    __syncthreads();
    v = sbuf[0] + sbuf[1] + sbuf[2] + sbuf[3];
    __syncthreads();
    return v;
}

// ---------------- instance norm + direct circular-shift fp16 emit ----------------
__global__ void instnorm_kernel(const float* __restrict__ x) {
    __shared__ float sbuf[4];
    int b = blockIdx.x >> 5, c = blockIdx.x & 31;
    int t = threadIdx.x;
    float v[4];
    #pragma unroll
    for (int u = 0; u < 4; ++u)
        v[u] = x[((size_t)b*SEQ + t + 128*u)*CIN + c];
    float s = v[0]+v[1]+v[2]+v[3];
    s = blockSum128(s, sbuf);
    float mean = s * (1.0f/SEQ);
    float qq = 0.f;
    #pragma unroll
    for (int u = 0; u < 4; ++u) { float d = v[u]-mean; qq += d*d; }
    qq = blockSum128(qq, sbuf);
    float sd = sqrtf(qq*(1.0f/SEQ) + 1e-5f);
    float inv = 1.0f/sd;
    #pragma unroll
    for (int u = 0; u < 4; ++u) {
        int l = t + 128*u;
        __half hv = __float2half_rn((v[u]-mean)*inv);
        // value at time l appears at rows (l+1)%SEQ (kk=0), l (kk=1), (l-1+SEQ)%SEQ (kk=2)
        size_t base = (size_t)b * SEQ * 128;
        g_xcat16[base + (size_t)((l + 1) & (SEQ-1)) * 128 + 0*32 + c] = hv;
        g_xcat16[base + (size_t)l * 128 + 1*32 + c] = hv;
        g_xcat16[base + (size_t)((l - 1 + SEQ) & (SEQ-1)) * 128 + 2*32 + c] = hv;
    }
    if (t == 0) { g_mean[b*CIN+c] = mean; g_std[b*CIN+c] = sd; }
}

// zero-pad columns 96..127 of xcat16 (once per replay; values never written there)
__global__ void xcat_pad_kernel() {
    int idx = blockIdx.x * 256 + threadIdx.x;   // NTOK*32
    if (idx >= NTOK * 32) return;
    int n = idx >> 5, r = 96 + (idx & 31);
    g_xcat16[(size_t)n * 128 + r] = __float2half_rn(0.f);
}

__global__ void wcat16_kernel(const float* __restrict__ cw) {
    int idx = blockIdx.x*256 + threadIdx.x;   // D_*128
    if (idx >= D_*128) return;
    int r = idx & 127, d = idx >> 7;
    float val = 0.f;
    if (r < 96) {
        int kk = r >> 5, c = r & 31;
        val = cw[(d*CIN + c)*3 + kk];
    }
    g_wcat16[idx] = __float2half_rn(val);
}

// ---------------- fp32 SGEMM (tiny final channel projection) ----------------
__global__ void __launch_bounds__(256, 2) gemm_f32(
    const float* __restrict__ A, const float* __restrict__ Bm,
    const float* __restrict__ bias, float* __restrict__ C,
    int M, int N, int K)
{
    __shared__ float As[16][132];
    __shared__ float Bs[16][132];
    int tid = threadIdx.x;
    int m0 = blockIdx.y * 128, n0 = blockIdx.x * 128;
    int tx = tid & 15, ty = tid >> 4;
    int lr = tid >> 2;
    int lq = (tid & 3) * 4;

    float acc[8][8];
    #pragma unroll
    for (int i = 0; i < 8; ++i)
        #pragma unroll
        for (int j = 0; j < 8; ++j) acc[i][j] = 0.f;

    for (int k0 = 0; k0 < K; k0 += 16) {
        #pragma unroll
        for (int hh = 0; hh < 2; ++hh) {
            int r = lr + hh*64;
            int gm = m0 + r;
            float4 va = make_float4(0.f,0.f,0.f,0.f);
            if (gm < M) va = *(const float4*)(A + (size_t)gm*K + k0 + lq);
            As[lq+0][r] = va.x; As[lq+1][r] = va.y; As[lq+2][r] = va.z; As[lq+3][r] = va.w;
            int gn = n0 + r;
            float4 vb = make_float4(0.f,0.f,0.f,0.f);
            if (gn < N) vb = *(const float4*)(Bm + (size_t)gn*K + k0 + lq);
            Bs[lq+0][r] = vb.x; Bs[lq+1][r] = vb.y; Bs[lq+2][r] = vb.z; Bs[lq+3][r] = vb.w;
        }
        __syncthreads();
        #pragma unroll
        for (int kk = 0; kk < 16; ++kk) {
            float4 a0 = *(const float4*)(&As[kk][ty*4]);
            float4 a1 = *(const float4*)(&As[kk][64 + ty*4]);
            float4 b0 = *(const float4*)(&Bs[kk][tx*4]);
            float4 b1 = *(const float4*)(&Bs[kk][64 + tx*4]);
            float av[8] = {a0.x,a0.y,a0.z,a0.w,a1.x,a1.y,a1.z,a1.w};
            float bv[8] = {b0.x,b0.y,b0.z,b0.w,b1.x,b1.y,b1.z,b1.w};
            #pragma unroll
            for (int i = 0; i < 8; ++i)
                #pragma unroll
                for (int j = 0; j < 8; ++j)
                    acc[i][j] = fmaf(av[i], bv[j], acc[i][j]);
        }
        __syncthreads();
    }

    #pragma unroll
    for (int i = 0; i < 8; ++i) {
        int mi = (i < 4) ? (ty*4 + i) : (64 + ty*4 + i - 4);
        int m = m0 + mi;
        if (m >= M) continue;
        #pragma unroll
        for (int j = 0; j < 8; ++j) {
            int nj = (j < 4) ? (tx*4 + j) : (64 + tx*4 + j - 4);
            int n = n0 + nj;
            if (n >= N) continue;
            C[(size_t)m*N + n] = acc[i][j] + bias[n];
        }
    }
}

// ---------------- fused (optional residual add) + LayerNorm + fp16 copy ----------------
__global__ void add_ln_kernel(const float* __restrict__ A, const float* __restrict__ R,
                              const float* __restrict__ g, const float* __restrict__ be,
                              float* __restrict__ out, __half* __restrict__ out16)
{
    __shared__ float sbuf[4];
    size_t n = blockIdx.x;
    int t = threadIdx.x;
    float4 v = ((const float4*)(A + n*D_))[t];
    if (R) {
        float4 r = ((const float4*)(R + n*D_))[t];
        v.x += r.x; v.y += r.y; v.z += r.z; v.w += r.w;
    }
    float s = v.x + v.y + v.z + v.w;
    s = blockSum128(s, sbuf);
    float mean = s * (1.0f/D_);
    float dx = v.x-mean, dy = v.y-mean, dz = v.z-mean, dw = v.w-mean;
    float qq = dx*dx + dy*dy + dz*dz + dw*dw;
    qq = blockSum128(qq, sbuf);
    float rstd = rsqrtf(qq*(1.0f/D_) + 1e-5f);
    float4 gv = ((const float4*)g)[t];
    float4 bv = ((const float4*)be)[t];
    float4 o;
    o.x = dx*rstd*gv.x + bv.x;
    o.y = dy*rstd*gv.y + bv.y;
    o.z = dz*rstd*gv.z + bv.z;
    o.w = dw*rstd*gv.w + bv.w;
    ((float4*)(out + n*D_))[t] = o;
    if (out16) {
        uint2 h;
        h.x = packh2(o.x, o.y);
        h.y = packh2(o.z, o.w);
        ((uint2*)(out16 + n*D_))[t] = h;
    }
}

// ---------------- time projection + de-normalization ----------------
__global__ void timeproj_kernel(const float* __restrict__ Wt, const float* __restrict__ bt,
                                float* __restrict__ out)
{
    __shared__ float sw[512];
    __shared__ float sred[4][32];
    int bp = blockIdx.x;
    int b = bp / PRED, p = bp % PRED;
    int t = threadIdx.x;
    for (int j = t; j < 512; j += 128) sw[j] = Wt[p*512 + j];
    __syncthreads();
    int c = t & 31, part = t >> 5;
    const float* dp = g_dec1 + (size_t)b*SEQ*CIN;
    float s = 0.f;
    for (int l = part*128; l < part*128 + 128; ++l)
        s += dp[l*CIN + c] * sw[l];
    sred[part][c] = s;
    __syncthreads();
    if (t < 32) {
        float tot = sred[0][c] + sred[1][c] + sred[2][c] + sred[3][c] + bt[p];
        out[((size_t)b*PRED + p)*CIN + c] = tot * g_std[b*CIN+c] + g_mean[b*CIN+c];
    }
}

// ---------------- launch ----------------
extern "C" void kernel_launch(void* const* d_in, const int* in_sizes, int n_in,
                              void* d_out, int out_size)
{
    const float* x_enc  = (const float*)d_in[0];
    const float* conv_w = (const float*)d_in[1];
    const float* Wq = (const float*)d_in[2];
    const float* Wk = (const float*)d_in[3];
    const float* Wv = (const float*)d_in[4];
    const float* Wo = (const float*)d_in[5];
    const float* bq = (const float*)d_in[6];
    const float* bk = (const float*)d_in[7];
    const float* bv = (const float*)d_in[8];
    const float* bo = (const float*)d_in[9];
    const float* ff1_w = (const float*)d_in[10];
    const float* ff1_b = (const float*)d_in[11];
    const float* ff2_w = (const float*)d_in[12];
    const float* ff2_b = (const float*)d_in[13];
    const float* n1_g = (const float*)d_in[14];
    const float* n1_b = (const float*)d_in[15];
    const float* n2_g = (const float*)d_in[16];
    const float* n2_b = (const float*)d_in[17];
    const float* fn_g = (const float*)d_in[18];
    const float* fn_b = (const float*)d_in[19];
    const float* Wch  = (const float*)d_in[20];
    const float* bch  = (const float*)d_in[21];
    const float* Wt   = (const float*)d_in[22];
    const float* bt   = (const float*)d_in[23];
    float* out = (float*)d_out;

    float *h, *tmp, *x1, *dec1, *bqkv;
    __half *h16, *x116, *attn16, *ff16, *xcat16, *wcat16, *w16;
    cudaGetSymbolAddress((void**)&h,    g_h);
    cudaGetSymbolAddress((void**)&tmp,  g_tmp);
    cudaGetSymbolAddress((void**)&x1,   g_x1);
    cudaGetSymbolAddress((void**)&dec1, g_dec1);
    cudaGetSymbolAddress((void**)&bqkv, g_bqkv);
    cudaGetSymbolAddress((void**)&h16,    g_h16);
    cudaGetSymbolAddress((void**)&x116,   g_x116);
    cudaGetSymbolAddress((void**)&attn16, g_attn16);
    cudaGetSymbolAddress((void**)&ff16,   g_ff16);
    cudaGetSymbolAddress((void**)&xcat16, g_xcat16);
    cudaGetSymbolAddress((void**)&wcat16, g_wcat16);
    cudaGetSymbolAddress((void**)&w16,    g_w16);

    cudaFuncSetAttribute(hgemm<EPI_PLAIN>, cudaFuncAttributeMaxDynamicSharedMemorySize, HG_SMEM);
    cudaFuncSetAttribute(hgemm<EPI_GELU>,  cudaFuncAttributeMaxDynamicSharedMemorySize, HG_SMEM);
    cudaFuncSetAttribute(hgemm<EPI_QKV>,   cudaFuncAttributeMaxDynamicSharedMemorySize, HG_SMEM);
    cudaFuncSetAttribute(hgemm<EPI_EMB>,   cudaFuncAttributeMaxDynamicSharedMemorySize, HG_SMEM);
    cudaFuncSetAttribute(fattn, cudaFuncAttributeMaxDynamicSharedMemorySize, AT_SMEM);

    convert_weights<<<(WTOT/4 + 255)/256, 256>>>(Wq, Wk, Wv, Wo, ff1_w, ff2_w);
    biascat_kernel<<<(3*1536 + 255)/256, 256>>>(bq, bk, bv);
    instnorm_kernel<<<B_*CIN, 128>>>(x_enc);
    xcat_pad_kernel<<<(NTOK*32)/256, 256>>>();
    wcat16_kernel<<<(D_*128)/256, 256>>>(conv_w);
    hgemm<EPI_EMB><<<dim3(4,128), 256, HG_SMEM>>>(xcat16, wcat16, nullptr, h, h16, NTOK, D_, 128);

    for (int i = 0; i < 3; ++i) {
        hgemm<EPI_QKV><<<dim3(12,128), 256, HG_SMEM>>>(h16, w16 + WOFF_QKV + (size_t)i*1536*512,
                                                       bqkv + i*1536, nullptr, nullptr, NTOK, 1536, D_);
        fattn<<<dim3(4, B_*H_), 256, AT_SMEM>>>();
        hgemm<EPI_PLAIN><<<dim3(4,128), 256, HG_SMEM>>>(attn16, w16+WOFF_WO+(size_t)i*D_*D_, bo+i*D_, tmp, nullptr, NTOK, D_, D_);
        add_ln_kernel<<<NTOK, 128>>>(h, tmp, n1_g+i*D_, n1_b+i*D_, x1, x116);
        hgemm<EPI_GELU><<<dim3(16,128), 256, HG_SMEM>>>(x116, w16+WOFF_F1+(size_t)i*DFF*D_, ff1_b+i*DFF, nullptr, ff16, NTOK, DFF, D_);
        hgemm<EPI_PLAIN><<<dim3(4,128), 256, HG_SMEM>>>(ff16, w16+WOFF_F2+(size_t)i*D_*DFF, ff2_b+i*D_, tmp, nullptr, NTOK, D_, DFF);
        add_ln_kernel<<<NTOK, 128>>>(x1, tmp, n2_g+i*D_, n2_b+i*D_, h, h16);
    }

    add_ln_kernel<<<NTOK, 128>>>(h, nullptr, fn_g, fn_b, h, nullptr);
    gemm_f32<<<dim3(1,128), 256>>>(h, Wch, bch, dec1, NTOK, CIN, D_);
    timeproj_kernel<<<B_*PRED, 128>>>(Wt, bt, out);
}